// round 11
// baseline (speedup 1.0000x reference)
#include <cuda_runtime.h>
#include <cuda_bf16.h>
#include <math.h>
#include <stdint.h>

#define BDIM 2
#define CDIM 2048
#define MDIM 1024
#define NTOK (BDIM*CDIM)
#define FDIM 4096
#define LN_EPS 1e-5f

// ---------------- scratch ----------------
__device__ __align__(256) float g_W1[MDIM*3072];
__device__ __align__(256) float g_W2[MDIM*2048];
__device__ __align__(256) float g_QKV[(size_t)NTOK*3072];
__device__ __align__(256) float g_V[(size_t)NTOK*MDIM];
__device__ __align__(256) float g_AO[(size_t)NTOK*MDIM];
__device__ __align__(256) float g_T[(size_t)NTOK*MDIM];
__device__ __align__(256) float g_N1[(size_t)NTOK*MDIM];
__device__ __align__(256) float g_N2[(size_t)NTOK*MDIM];
__device__ __align__(256) __nv_bfloat16 g_Ah[(size_t)NTOK*MDIM];
__device__ __align__(256) __nv_bfloat16 g_Al[(size_t)NTOK*MDIM];
__device__ __align__(256) __nv_bfloat16 g_Bh[(size_t)FDIM*MDIM];
__device__ __align__(256) __nv_bfloat16 g_Bl[(size_t)FDIM*MDIM];
__device__ __align__(256) __nv_bfloat16 g_Ch[(size_t)NTOK*FDIM];
__device__ __align__(256) __nv_bfloat16 g_Cl[(size_t)NTOK*FDIM];

// ---------------- helpers ----------------
__device__ __forceinline__ uint32_t smem_u32(const void* p) {
    uint32_t a;
    asm("{ .reg .u64 t; cvta.to.shared.u64 t, %1; cvt.u32.u64 %0, t; }" : "=r"(a) : "l"(p));
    return a;
}
__device__ __forceinline__ void cp16(uint32_t dst, const void* src) {
    asm volatile("cp.async.cg.shared.global [%0], [%1], 16;" :: "r"(dst), "l"(src));
}
#define CP_COMMIT() asm volatile("cp.async.commit_group;" ::: "memory")
__device__ __forceinline__ uint32_t swz(uint32_t off) { return off ^ ((off >> 3) & 0x70); }

__device__ __forceinline__ void ldsm4(uint32_t* r, uint32_t addr) {
    asm volatile("ldmatrix.sync.aligned.m8n8.x4.shared.b16 {%0,%1,%2,%3}, [%4];"
        : "=r"(r[0]), "=r"(r[1]), "=r"(r[2]), "=r"(r[3]) : "r"(addr));
}
__device__ __forceinline__ void mma16816(float* c, const uint32_t* a, const uint32_t* b) {
    asm volatile("mma.sync.aligned.m16n8k16.row.col.f32.bf16.bf16.f32 "
        "{%0,%1,%2,%3}, {%4,%5,%6,%7}, {%8,%9}, {%0,%1,%2,%3};"
        : "+f"(c[0]), "+f"(c[1]), "+f"(c[2]), "+f"(c[3])
        : "r"(a[0]), "r"(a[1]), "r"(a[2]), "r"(a[3]), "r"(b[0]), "r"(b[1]));
}

// ---------------- prep kernels ----------------
__global__ __launch_bounds__(256) void repack_kernel(
    const float* __restrict__ wq, const float* __restrict__ wk,
    const float* __restrict__ wv, float* __restrict__ W)
{
    int i = blockIdx.x * 256 + threadIdx.x;
    int m = i >> 10, col = i & 1023;
    int src = (((col >> 6) * MDIM + m) << 6) + (col & 63);
    float* dst = W + (size_t)m * 3072 + col;
    dst[0]    = wq[src];
    dst[1024] = wk[src];
    dst[2048] = wv[src];
}

__global__ __launch_bounds__(256) void repack_qk_kernel(
    const float* __restrict__ wq, const float* __restrict__ wk, float* __restrict__ W)
{
    int i = blockIdx.x * 256 + threadIdx.x;
    int m = i >> 10, col = i & 1023;
    int src = (((col >> 6) * MDIM + m) << 6) + (col & 63);
    W[(size_t)m * 2048 + col]        = wq[src];
    W[(size_t)m * 2048 + 1024 + col] = wk[src];
}

__global__ __launch_bounds__(256) void split_kernel(
    const float* __restrict__ in, __nv_bfloat16* __restrict__ hi,
    __nv_bfloat16* __restrict__ lo, int n)
{
    int i = (blockIdx.x * 256 + threadIdx.x) * 4;
    if (i >= n) return;
    float4 v = *(const float4*)(in + i);
    float x[4] = {v.x, v.y, v.z, v.w};
    __nv_bfloat16 h[4], l[4];
#pragma unroll
    for (int j = 0; j < 4; j++) {
        h[j] = __float2bfloat16(x[j]);
        l[j] = __float2bfloat16(x[j] - __bfloat162float(h[j]));
    }
    __nv_bfloat162 a, b, c, d;
    a.x = h[0]; a.y = h[1]; b.x = h[2]; b.y = h[3];
    c.x = l[0]; c.y = l[1]; d.x = l[2]; d.y = l[3];
    ((__nv_bfloat162*)(hi + i))[0] = a; ((__nv_bfloat162*)(hi + i))[1] = b;
    ((__nv_bfloat162*)(lo + i))[0] = c; ((__nv_bfloat162*)(lo + i))[1] = d;
}

__global__ void tsplit_kernel(const float* __restrict__ in,
    __nv_bfloat16* __restrict__ hi, __nv_bfloat16* __restrict__ lo, int K, int P)
{
    __shared__ float tile[32][33];
    int p0 = blockIdx.x * 32, k0 = blockIdx.y * 32;
    int tx = threadIdx.x, ty = threadIdx.y;
#pragma unroll
    for (int j = 0; j < 4; j++)
        tile[ty + j * 8][tx] = in[(size_t)(k0 + ty + j * 8) * P + p0 + tx];
    __syncthreads();
#pragma unroll
    for (int j = 0; j < 4; j++) {
        int p = p0 + ty + j * 8, k = k0 + tx;
        float x = tile[tx][ty + j * 8];
        __nv_bfloat16 h = __float2bfloat16(x);
        hi[(size_t)p * K + k] = h;
        lo[(size_t)p * K + k] = __float2bfloat16(x - __bfloat162float(h));
    }
}

__global__ __launch_bounds__(256) void wvsplit_kernel(
    const float* __restrict__ wv, __nv_bfloat16* __restrict__ hi, __nv_bfloat16* __restrict__ lo)
{
    int idx = blockIdx.x * 256 + threadIdx.x;
    int p = idx >> 10, k = idx & 1023;
    float x = wv[(size_t)(((p >> 6) * MDIM + k) << 6) + (p & 63)];
    __nv_bfloat16 h = __float2bfloat16(x);
    hi[idx] = h;
    lo[idx] = __float2bfloat16(x - __bfloat162float(h));
}

// ---------------- split-bf16 HMMA GEMM (unchanged) ----------------
#define MMA_STAGE 65536
#define MMA_SMEM  (2*MMA_STAGE + 1024)

__device__ __forceinline__ void stage_load(uint32_t sb,
    const __nv_bfloat16* Ah, const __nv_bfloat16* Al,
    const __nv_bfloat16* Bh, const __nv_bfloat16* Bl,
    int Kdim, int kofs, int rowA, int colB, int t)
{
#pragma unroll
    for (int j = 0; j < 4; j++) {
        int g = j * 256 + t;
        int r = g >> 3, c16 = g & 7;
        uint32_t sw = swz((uint32_t)(r * 128 + c16 * 16));
        size_t ao = (size_t)(rowA + r) * Kdim + kofs + c16 * 8;
        size_t bo = (size_t)(colB + r) * Kdim + kofs + c16 * 8;
        cp16(sb + sw,         Ah + ao);
        cp16(sb + 16384 + sw, Al + ao);
        cp16(sb + 32768 + sw, Bh + bo);
        cp16(sb + 49152 + sw, Bl + bo);
    }
}

__global__ __launch_bounds__(256, 1) void mma_gemm_kernel(
    const __nv_bfloat16* __restrict__ Ah, const __nv_bfloat16* __restrict__ Al,
    const __nv_bfloat16* __restrict__ Bh, const __nv_bfloat16* __restrict__ Bl,
    const float* __restrict__ bias, float* __restrict__ C,
    __nv_bfloat16* __restrict__ outH, __nv_bfloat16* __restrict__ outL,
    int Kdim, int ldc, int relu)
{
    extern __shared__ char dynsm[];
    uint32_t sd = (smem_u32(dynsm) + 1023u) & ~1023u;

    int t = threadIdx.x, wid = t >> 5, lane = t & 31;
    int warp_m = wid & 1, warp_n = wid >> 1;
    int rowA = blockIdx.y * 128, colB = blockIdx.x * 128;

    float acc[4][4][4];
#pragma unroll
    for (int i = 0; i < 4; i++)
#pragma unroll
        for (int j = 0; j < 4; j++)
#pragma unroll
            for (int k = 0; k < 4; k++) acc[i][j][k] = 0.f;

    int rA = lane & 15;
    int cA = (lane >> 4) << 3;
    int rB = (lane & 7) + ((lane >> 4) << 3);
    int cB = lane & 8;

    int nc = Kdim >> 6;
    stage_load(sd, Ah, Al, Bh, Bl, Kdim, 0, rowA, colB, t);
    CP_COMMIT();

    for (int c = 0; c < nc; c++) {
        if (c + 1 < nc) {
            stage_load(sd + ((c + 1) & 1) * MMA_STAGE, Ah, Al, Bh, Bl,
                       Kdim, (c + 1) << 6, rowA, colB, t);
            CP_COMMIT();
            asm volatile("cp.async.wait_group 1;" ::: "memory");
        } else {
            asm volatile("cp.async.wait_group 0;" ::: "memory");
        }
        __syncthreads();
        uint32_t base = sd + (c & 1) * MMA_STAGE;

#pragma unroll
        for (int ks = 0; ks < 4; ks++) {
            int Kc = ks * 16;
            uint32_t aH[4][4], aL[4][4], bH[4][2], bL[4][2];
#pragma unroll
            for (int mt = 0; mt < 4; mt++) {
                uint32_t sw = swz((uint32_t)((warp_m * 64 + mt * 16 + rA) * 128 + (Kc + cA) * 2));
                ldsm4(aH[mt], base + sw);
                ldsm4(aL[mt], base + 16384 + sw);
            }
#pragma unroll
            for (int p = 0; p < 2; p++) {
                uint32_t sw = swz((uint32_t)((warp_n * 32 + p * 16 + rB) * 128 + (Kc + cB) * 2));
                uint32_t q[4];
                ldsm4(q, base + 32768 + sw);
                bH[2*p][0] = q[0]; bH[2*p][1] = q[1]; bH[2*p+1][0] = q[2]; bH[2*p+1][1] = q[3];
                ldsm4(q, base + 49152 + sw);
                bL[2*p][0] = q[0]; bL[2*p][1] = q[1]; bL[2*p+1][0] = q[2]; bL[2*p+1][1] = q[3];
            }
#pragma unroll
            for (int mt = 0; mt < 4; mt++)
#pragma unroll
                for (int nt = 0; nt < 4; nt++) {
                    mma16816(acc[mt][nt], aH[mt], bH[nt]);
                    mma16816(acc[mt][nt], aH[mt], bL[nt]);
                    mma16816(acc[mt][nt], aL[mt], bH[nt]);
                }
        }
        __syncthreads();
    }

    int r0 = rowA + warp_m * 64 + (lane >> 2);
    int c0 = colB + warp_n * 32 + (lane & 3) * 2;
#pragma unroll
    for (int mt = 0; mt < 4; mt++) {
#pragma unroll
        for (int nt = 0; nt < 4; nt++) {
            int col = c0 + nt * 8;
            float bb0 = 0.f, bb1 = 0.f;
            if (bias) { bb0 = bias[col]; bb1 = bias[col + 1]; }
            float v0 = acc[mt][nt][0] + bb0;
            float v1 = acc[mt][nt][1] + bb1;
            float v2 = acc[mt][nt][2] + bb0;
            float v3 = acc[mt][nt][3] + bb1;
            if (relu) {
                v0 = fmaxf(v0, 0.f); v1 = fmaxf(v1, 0.f);
                v2 = fmaxf(v2, 0.f); v3 = fmaxf(v3, 0.f);
            }
            size_t ra = (size_t)(r0 + mt * 16) * ldc + col;
            size_t rb = ra + 8 * (size_t)ldc;
            if (outH) {
                __nv_bfloat162 h, l;
                h.x = __float2bfloat16(v0); h.y = __float2bfloat16(v1);
                l.x = __float2bfloat16(v0 - __bfloat162float(h.x));
                l.y = __float2bfloat16(v1 - __bfloat162float(h.y));
                *(__nv_bfloat162*)&outH[ra] = h;
                *(__nv_bfloat162*)&outL[ra] = l;
                h.x = __float2bfloat16(v2); h.y = __float2bfloat16(v3);
                l.x = __float2bfloat16(v2 - __bfloat162float(h.x));
                l.y = __float2bfloat16(v3 - __bfloat162float(h.y));
                *(__nv_bfloat162*)&outH[rb] = h;
                *(__nv_bfloat162*)&outL[rb] = l;
            } else {
                *(float2*)&C[ra] = make_float2(v0, v1);
                *(float2*)&C[rb] = make_float2(v2, v3);
            }
        }
    }
}

// ---------------- fp32 SGEMM (unchanged — bit-identical logit path) ----------------
__global__ __launch_bounds__(256) void sgemm_kernel(
    const float* __restrict__ A, const float* __restrict__ B,
    float* __restrict__ C, int Kdim, int lda, int ldb, int ldc)
{
    __shared__ float sA[16][128];
    __shared__ float sB[16][128];

    int t = threadIdx.x;
    int tx = t & 15, ty = t >> 4;
    int rowBase = blockIdx.y * 128, colBase = blockIdx.x * 128;

    float acc[8][8];
#pragma unroll
    for (int i = 0; i < 8; i++)
#pragma unroll
        for (int j = 0; j < 8; j++) acc[i][j] = 0.f;

    int arow = t >> 1, acol = (t & 1) * 4;
    int brow = t >> 5, bcol = (t & 31) * 4;
    const float* Aptr = A + (size_t)(rowBase + arow) * lda + acol;
    const float* Bptr = B + (size_t)brow * ldb + colBase + bcol;

    for (int kt = 0; kt < Kdim; kt += 16) {
        float4 a0 = *(const float4*)(Aptr);
        float4 a1 = *(const float4*)(Aptr + 8);
        float4 b0 = *(const float4*)(Bptr);
        float4 b1 = *(const float4*)(Bptr + 8 * (size_t)ldb);
        sA[acol+0][arow]=a0.x; sA[acol+1][arow]=a0.y; sA[acol+2][arow]=a0.z; sA[acol+3][arow]=a0.w;
        sA[acol+8][arow]=a1.x; sA[acol+9][arow]=a1.y; sA[acol+10][arow]=a1.z; sA[acol+11][arow]=a1.w;
        *(float4*)&sB[brow][bcol] = b0;
        *(float4*)&sB[brow+8][bcol] = b1;
        __syncthreads();
#pragma unroll
        for (int k = 0; k < 16; k++) {
            float4 x0 = *(const float4*)&sA[k][ty*4];
            float4 x1 = *(const float4*)&sA[k][64+ty*4];
            float4 y0 = *(const float4*)&sB[k][tx*4];
            float4 y1 = *(const float4*)&sB[k][64+tx*4];
            float av[8] = {x0.x,x0.y,x0.z,x0.w,x1.x,x1.y,x1.z,x1.w};
            float bv[8] = {y0.x,y0.y,y0.z,y0.w,y1.x,y1.y,y1.z,y1.w};
#pragma unroll
            for (int i = 0; i < 8; i++)
#pragma unroll
                for (int j = 0; j < 8; j++)
                    acc[i][j] = fmaf(av[i], bv[j], acc[i][j]);
        }
        __syncthreads();
        Aptr += 16;
        Bptr += 16 * (size_t)ldb;
    }
    int c0 = colBase + tx * 4, c1 = colBase + 64 + tx * 4;
#pragma unroll
    for (int i = 0; i < 8; i++) {
        int r = rowBase + ((i < 4) ? (ty*4+i) : (64+ty*4+i-4));
        *(float4*)&C[(size_t)r*ldc + c0] = make_float4(acc[i][0],acc[i][1],acc[i][2],acc[i][3]);
        *(float4*)&C[(size_t)r*ldc + c1] = make_float4(acc[i][4],acc[i][5],acc[i][6],acc[i][7]);
    }
}

// ---------------- attention v3: 8q x 4k register tile (1.5 B/FMA), 128 threads ----------------
// Math (per-element fma order, softmax grouping, mask) is bit-identical to R10.
#define QP 68
#define SQT_OFF   0
#define SKT_OFF   4352
#define SP_OFF    8704
#define SKRAW_OFF 13056
#define SV_OFF    17152
#define ATT_SMEM_BYTES ((SV_OFF + 2*4096) * 4)   // 101376 B

__global__ __launch_bounds__(128, 2) void attn_kernel(
    const float* __restrict__ Qb, int qs,
    const float* __restrict__ Kb, int ks_,
    const float* __restrict__ Vb, int vs,
    float* __restrict__ AO, int masked)
{
    extern __shared__ float sm[];
    float* sQT   = sm + SQT_OFF;
    float* sKT   = sm + SKT_OFF;
    float* sP    = sm + SP_OFF;
    float* sKraw = sm + SKRAW_OFF;
    uint32_t sbase = smem_u32(sm);
    uint32_t kraw_b = sbase + SKRAW_OFF * 4;
    uint32_t v_b0   = sbase + SV_OFF * 4;

    int t = threadIdx.x;              // 128 threads
    int tx = t & 15, ty = t >> 4;     // tx 0..15 (keys), ty 0..7 (queries)
    int tx4 = tx * 4, ty8 = ty * 8;
    int q0 = blockIdx.x * 64;
    int b = blockIdx.y >> 4, h = blockIdx.y & 15;

    const float* qbase = Qb + (size_t)b * CDIM * qs + h * 64;
    const float* kbase = Kb + (size_t)b * CDIM * ks_ + h * 64;
    const float* vbase = Vb + (size_t)b * CDIM * vs + h * 64;

    // prefetch tile 0 (K raw + V buf0): 1024 chunks / 128 threads = 8 iters
#pragma unroll
    for (int it = 0; it < 8; it++) {
        int idx = it * 128 + t;
        int row = idx >> 4, ch = idx & 15;
        cp16(kraw_b + row * 256 + ch * 16, kbase + (size_t)row * ks_ + ch * 4);
        cp16(v_b0 + row * 256 + ch * 16, vbase + (size_t)row * vs + ch * 4);
    }
    CP_COMMIT();

    // load Q transposed (d-major)
#pragma unroll
    for (int it = 0; it < 8; it++) {
        int idx = it * 128 + t;
        int qi = idx >> 4, dg = idx & 15;
        float4 v = *(const float4*)&qbase[(size_t)(q0 + qi) * qs + dg * 4];
        sQT[(dg * 4 + 0) * QP + qi] = v.x;
        sQT[(dg * 4 + 1) * QP + qi] = v.y;
        sQT[(dg * 4 + 2) * QP + qi] = v.z;
        sQT[(dg * 4 + 3) * QP + qi] = v.w;
    }

    float m_run[8], l_run[8], o[8][4];
#pragma unroll
    for (int i = 0; i < 8; i++) {
        m_run[i] = -INFINITY; l_run[i] = 0.f;
#pragma unroll
        for (int j = 0; j < 4; j++) o[i][j] = 0.f;
    }

    for (int kt = 0; kt < 32; kt++) {
        int cur = kt & 1;
        int k0 = kt * 64;
        asm volatile("cp.async.wait_group 0;" ::: "memory");
        __syncthreads();

        // transpose K tile into d-major with 4-col XOR swizzle
#pragma unroll
        for (int it = 0; it < 8; it++) {
            int idx = it * 128 + t;
            int kj = idx >> 4, dg = idx & 15;
            float4 v = *(const float4*)&sKraw[kj * 64 + dg * 4];
            int col = kj ^ ((dg & 7) << 2);
            sKT[(dg * 4 + 0) * QP + col] = v.x;
            sKT[(dg * 4 + 1) * QP + col] = v.y;
            sKT[(dg * 4 + 2) * QP + col] = v.z;
            sKT[(dg * 4 + 3) * QP + col] = v.w;
        }
        __syncthreads();

        // prefetch next tile
        if (kt + 1 < 32) {
            int k0n = k0 + 64;
            uint32_t vdst = v_b0 + (cur ^ 1) * 16384;
#pragma unroll
            for (int it = 0; it < 8; it++) {
                int idx = it * 128 + t;
                int row = idx >> 4, ch = idx & 15;
                cp16(kraw_b + row * 256 + ch * 16, kbase + (size_t)(k0n + row) * ks_ + ch * 4);
                cp16(vdst + row * 256 + ch * 16, vbase + (size_t)(k0n + row) * vs + ch * 4);
            }
            CP_COMMIT();
        }

        // ---- S = Q K^T : 8q x 4k per thread, d ascending (order identical) ----
        float s[8][4];
#pragma unroll
        for (int i = 0; i < 8; i++)
#pragma unroll
            for (int j = 0; j < 4; j++) s[i][j] = 0.f;

#pragma unroll 2
        for (int dg = 0; dg < 16; dg++) {
            int colx = tx4 ^ ((dg & 7) << 2);
#pragma unroll
            for (int e = 0; e < 4; e++) {
                int d = dg * 4 + e;
                float4 a0 = *(const float4*)&sQT[d * QP + ty8];
                float4 a1 = *(const float4*)&sQT[d * QP + ty8 + 4];
                float4 bq = *(const float4*)&sKT[d * QP + colx];
                s[0][0] = fmaf(a0.x, bq.x, s[0][0]); s[0][1] = fmaf(a0.x, bq.y, s[0][1]);
                s[0][2] = fmaf(a0.x, bq.z, s[0][2]); s[0][3] = fmaf(a0.x, bq.w, s[0][3]);
                s[1][0] = fmaf(a0.y, bq.x, s[1][0]); s[1][1] = fmaf(a0.y, bq.y, s[1][1]);
                s[1][2] = fmaf(a0.y, bq.z, s[1][2]); s[1][3] = fmaf(a0.y, bq.w, s[1][3]);
                s[2][0] = fmaf(a0.z, bq.x, s[2][0]); s[2][1] = fmaf(a0.z, bq.y, s[2][1]);
                s[2][2] = fmaf(a0.z, bq.z, s[2][2]); s[2][3] = fmaf(a0.z, bq.w, s[2][3]);
                s[3][0] = fmaf(a0.w, bq.x, s[3][0]); s[3][1] = fmaf(a0.w, bq.y, s[3][1]);
                s[3][2] = fmaf(a0.w, bq.z, s[3][2]); s[3][3] = fmaf(a0.w, bq.w, s[3][3]);
                s[4][0] = fmaf(a1.x, bq.x, s[4][0]); s[4][1] = fmaf(a1.x, bq.y, s[4][1]);
                s[4][2] = fmaf(a1.x, bq.z, s[4][2]); s[4][3] = fmaf(a1.x, bq.w, s[4][3]);
                s[5][0] = fmaf(a1.y, bq.x, s[5][0]); s[5][1] = fmaf(a1.y, bq.y, s[5][1]);
                s[5][2] = fmaf(a1.y, bq.z, s[5][2]); s[5][3] = fmaf(a1.y, bq.w, s[5][3]);
                s[6][0] = fmaf(a1.z, bq.x, s[6][0]); s[6][1] = fmaf(a1.z, bq.y, s[6][1]);
                s[6][2] = fmaf(a1.z, bq.z, s[6][2]); s[6][3] = fmaf(a1.z, bq.w, s[6][3]);
                s[7][0] = fmaf(a1.w, bq.x, s[7][0]); s[7][1] = fmaf(a1.w, bq.y, s[7][1]);
                s[7][2] = fmaf(a1.w, bq.z, s[7][2]); s[7][3] = fmaf(a1.w, bq.w, s[7][3]);
            }
        }

        // ---- mask + scale + online softmax (same 64-key grouping, same shfl tree) ----
#pragma unroll
        for (int i = 0; i < 8; i++) {
            int qg = q0 + ty8 + i;
#pragma unroll
            for (int j = 0; j < 4; j++) {
                if (masked && (k0 + tx4 + j) <= qg) s[i][j] -= 100.f;
                s[i][j] *= 0.125f;
            }
            float mx = fmaxf(fmaxf(s[i][0], s[i][1]), fmaxf(s[i][2], s[i][3]));
#pragma unroll
            for (int off = 8; off >= 1; off >>= 1)
                mx = fmaxf(mx, __shfl_xor_sync(0xffffffffu, mx, off, 16));
            float mnew = fmaxf(m_run[i], mx);
            float p0 = expf(s[i][0] - mnew);
            float p1 = expf(s[i][1] - mnew);
            float p2 = expf(s[i][2] - mnew);
            float p3 = expf(s[i][3] - mnew);
            float rs = p0 + p1 + p2 + p3;
#pragma unroll
            for (int off = 8; off >= 1; off >>= 1)
                rs += __shfl_xor_sync(0xffffffffu, rs, off, 16);
            float corr = expf(m_run[i] - mnew);
            l_run[i] = l_run[i] * corr + rs;
            m_run[i] = mnew;
#pragma unroll
            for (int j = 0; j < 4; j++) o[i][j] *= corr;
            *(float4*)&sP[(ty8 + i) * QP + tx4] = make_float4(p0, p1, p2, p3);
        }
        __syncthreads();

        // ---- O += P V : 8q x 4v per thread, kj ascending (order identical) ----
        const float* sVc = sm + SV_OFF + cur * 4096;
#pragma unroll 2
        for (int kj0 = 0; kj0 < 64; kj0 += 4) {
            float4 pa[8];
#pragma unroll
            for (int i = 0; i < 8; i++)
                pa[i] = *(const float4*)&sP[(ty8 + i) * QP + kj0];
#pragma unroll
            for (int e = 0; e < 4; e++) {
                float4 bv = *(const float4*)&sVc[(kj0 + e) * 64 + tx4];
#pragma unroll
                for (int i = 0; i < 8; i++) {
                    float a = ((const float*)&pa[i])[e];
                    o[i][0] = fmaf(a, bv.x, o[i][0]);
                    o[i][1] = fmaf(a, bv.y, o[i][1]);
                    o[i][2] = fmaf(a, bv.z, o[i][2]);
                    o[i][3] = fmaf(a, bv.w, o[i][3]);
                }
            }
        }
    }

#pragma unroll
    for (int i = 0; i < 8; i++) {
        float inv = 1.f / l_run[i];
        size_t row = (size_t)(b * CDIM + q0 + ty8 + i) * MDIM + h * 64 + tx4;
#pragma unroll
        for (int j = 0; j < 4; j++) AO[row + j] = o[i][j] * inv;
    }
}

// ---------------- residual add + LayerNorm (unchanged) ----------------
__global__ __launch_bounds__(256) void addln_kernel(
    const float* __restrict__ X, const float* __restrict__ Y,
    const float* __restrict__ g, const float* __restrict__ bta,
    float* __restrict__ out)
{
    __shared__ float red[8];
    int row = blockIdx.x;
    int t = threadIdx.x;
    int lane = t & 31, wid = t >> 5;
    const float* xr = X + (size_t)row * MDIM;
    const float* yr = Y + (size_t)row * MDIM;

    float v[4];
#pragma unroll
    for (int i = 0; i < 4; i++) v[i] = xr[t + 256 * i] + yr[t + 256 * i];

    float s = v[0] + v[1] + v[2] + v[3];
#pragma unroll
    for (int off = 16; off >= 1; off >>= 1) s += __shfl_xor_sync(0xffffffffu, s, off);
    if (lane == 0) red[wid] = s;
    __syncthreads();
    float tot = 0.f;
#pragma unroll
    for (int i = 0; i < 8; i++) tot += red[i];
    float mu = tot * (1.f / 1024.f);
    __syncthreads();

    float q = 0.f;
#pragma unroll
    for (int i = 0; i < 4; i++) { float d = v[i] - mu; q += d * d; }
#pragma unroll
    for (int off = 16; off >= 1; off >>= 1) q += __shfl_xor_sync(0xffffffffu, q, off);
    if (lane == 0) red[wid] = q;
    __syncthreads();
    float qtot = 0.f;
#pragma unroll
    for (int i = 0; i < 8; i++) qtot += red[i];
    float inv = rsqrtf(qtot * (1.f / 1024.f) + LN_EPS);

#pragma unroll
    for (int i = 0; i < 4; i++) {
        int c = t + 256 * i;
        out[(size_t)row * MDIM + c] = (v[i] - mu) * inv * g[c] + bta[c];
    }
}

// ---------------- launcher ----------------
extern "C" void kernel_launch(void* const* d_in, const int* in_sizes, int n_in,
                              void* d_out, int out_size)
{
    const float* enc = (const float*)d_in[0];
    const float* x   = (const float*)d_in[1];
    const float* wq1 = (const float*)d_in[2];
    const float* wk1 = (const float*)d_in[3];
    const float* wv1 = (const float*)d_in[4];
    const float* wo1 = (const float*)d_in[5];
    const float* g1  = (const float*)d_in[6];
    const float* b1  = (const float*)d_in[7];
    const float* wq2 = (const float*)d_in[8];
    const float* wk2 = (const float*)d_in[9];
    const float* wv2 = (const float*)d_in[10];
    const float* wo2 = (const float*)d_in[11];
    const float* g2  = (const float*)d_in[12];
    const float* b2  = (const float*)d_in[13];
    const float* fw1 = (const float*)d_in[14];
    const float* fb1 = (const float*)d_in[15];
    const float* fw2 = (const float*)d_in[16];
    const float* fb2 = (const float*)d_in[17];
    const float* g3  = (const float*)d_in[18];
    const float* b3  = (const float*)d_in[19];
    float* out = (float*)d_out;

    float *W1, *W2, *QKV, *V, *AO, *T, *N1, *N2;
    __nv_bfloat16 *Ah, *Al, *Bh, *Bl, *Ch, *Cl;
    cudaGetSymbolAddress((void**)&W1, g_W1);
    cudaGetSymbolAddress((void**)&W2, g_W2);
    cudaGetSymbolAddress((void**)&QKV, g_QKV);
    cudaGetSymbolAddress((void**)&V,  g_V);
    cudaGetSymbolAddress((void**)&AO, g_AO);
    cudaGetSymbolAddress((void**)&T,  g_T);
    cudaGetSymbolAddress((void**)&N1, g_N1);
    cudaGetSymbolAddress((void**)&N2, g_N2);
    cudaGetSymbolAddress((void**)&Ah, g_Ah);
    cudaGetSymbolAddress((void**)&Al, g_Al);
    cudaGetSymbolAddress((void**)&Bh, g_Bh);
    cudaGetSymbolAddress((void**)&Bl, g_Bl);
    cudaGetSymbolAddress((void**)&Ch, g_Ch);
    cudaGetSymbolAddress((void**)&Cl, g_Cl);

    cudaFuncSetAttribute(attn_kernel, cudaFuncAttributeMaxDynamicSharedMemorySize, ATT_SMEM_BYTES);
    cudaFuncSetAttribute(mma_gemm_kernel, cudaFuncAttributeMaxDynamicSharedMemorySize, MMA_SMEM);

    dim3 tsb(32, 8);

    // weight repacks
    repack_kernel<<<4096, 256>>>(wq1, wk1, wv1, W1);
    repack_qk_kernel<<<4096, 256>>>(wq2, wk2, W2);

    // ---- masked self attention (all fp32 — feeds N1, logit-critical) ----
    sgemm_kernel<<<dim3(24, 32), 256>>>(x, W1, QKV, 1024, 1024, 3072, 3072);
    attn_kernel<<<dim3(32, 32), 128, ATT_SMEM_BYTES>>>(
        QKV, 3072, QKV + 1024, 3072, QKV + 2048, 3072, AO, 1);
    sgemm_kernel<<<dim3(8, 32), 256>>>(AO, wo1, T, 1024, 1024, 1024, 1024);
    addln_kernel<<<4096, 256>>>(x, T, g1, b1, N1);

    // ---- cross attention: Q/K fp32 (logit-critical), V2/wo2 on tensor ----
    sgemm_kernel<<<dim3(8, 32), 256>>>(N1, W2, QKV, 1024, 1024, 2048, 2048);
    sgemm_kernel<<<dim3(8, 32), 256>>>(enc, W2 + 1024, QKV + 1024, 1024, 1024, 2048, 2048);
    wvsplit_kernel<<<4096, 256>>>(wv2, Bh, Bl);
    split_kernel<<<4096, 256>>>(enc, Ah, Al, NTOK * MDIM);
    mma_gemm_kernel<<<dim3(8, 32), 256, MMA_SMEM>>>(
        Ah, Al, Bh, Bl, nullptr, V, nullptr, nullptr, 1024, 1024, 0);
    attn_kernel<<<dim3(32, 32), 128, ATT_SMEM_BYTES>>>(
        QKV, 2048, QKV + 1024, 2048, V, 1024, AO, 0);
    tsplit_kernel<<<dim3(32, 32), tsb>>>(wo2, Bh, Bl, 1024, 1024);
    split_kernel<<<4096, 256>>>(AO, Ah, Al, NTOK * MDIM);
    mma_gemm_kernel<<<dim3(8, 32), 256, MMA_SMEM>>>(
        Ah, Al, Bh, Bl, nullptr, T, nullptr, nullptr, 1024, 1024, 0);
    addln_kernel<<<4096, 256>>>(N1, T, g2, b2, N2);

    // ---- FFN (tensor; FFN1 writes split bf16 directly) ----
    tsplit_kernel<<<dim3(128, 32), tsb>>>(fw1, Bh, Bl, 1024, 4096);
    split_kernel<<<4096, 256>>>(N2, Ah, Al, NTOK * MDIM);
    mma_gemm_kernel<<<dim3(32, 32), 256, MMA_SMEM>>>(
        Ah, Al, Bh, Bl, fb1, nullptr, Ch, Cl, 1024, 4096, 1);
    tsplit_kernel<<<dim3(32, 128), tsb>>>(fw2, Bh, Bl, 4096, 1024);
    mma_gemm_kernel<<<dim3(8, 32), 256, MMA_SMEM>>>(
        Ch, Cl, Bh, Bl, fb2, T, nullptr, nullptr, 4096, 1024, 0);
    addln_kernel<<<4096, 256>>>(N2, T, g3, b3, out);
}

// round 13
// speedup vs baseline: 1.0429x; 1.0429x over previous
#include <cuda_runtime.h>
#include <cuda_bf16.h>
#include <math.h>
#include <stdint.h>

#define BDIM 2
#define CDIM 2048
#define MDIM 1024
#define NTOK (BDIM*CDIM)
#define FDIM 4096
#define LN_EPS 1e-5f

// ---------------- scratch ----------------
__device__ __align__(256) float g_W1[MDIM*3072];
__device__ __align__(256) float g_W2[MDIM*2048];
__device__ __align__(256) float g_QKV[(size_t)NTOK*3072];
__device__ __align__(256) float g_V[(size_t)NTOK*MDIM];
__device__ __align__(256) float g_AO[(size_t)NTOK*MDIM];
__device__ __align__(256) float g_T[(size_t)NTOK*MDIM];
__device__ __align__(256) float g_N1[(size_t)NTOK*MDIM];
__device__ __align__(256) float g_N2[(size_t)NTOK*MDIM];
__device__ __align__(256) __nv_bfloat16 g_Ah[(size_t)NTOK*MDIM];
__device__ __align__(256) __nv_bfloat16 g_Al[(size_t)NTOK*MDIM];
__device__ __align__(256) __nv_bfloat16 g_Bh[(size_t)FDIM*MDIM];
__device__ __align__(256) __nv_bfloat16 g_Bl[(size_t)FDIM*MDIM];
__device__ __align__(256) __nv_bfloat16 g_Ch[(size_t)NTOK*FDIM];
__device__ __align__(256) __nv_bfloat16 g_Cl[(size_t)NTOK*FDIM];

// ---------------- helpers ----------------
__device__ __forceinline__ uint32_t smem_u32(const void* p) {
    uint32_t a;
    asm("{ .reg .u64 t; cvta.to.shared.u64 t, %1; cvt.u32.u64 %0, t; }" : "=r"(a) : "l"(p));
    return a;
}
__device__ __forceinline__ void cp16(uint32_t dst, const void* src) {
    asm volatile("cp.async.cg.shared.global [%0], [%1], 16;" :: "r"(dst), "l"(src));
}
#define CP_COMMIT() asm volatile("cp.async.commit_group;" ::: "memory")
__device__ __forceinline__ uint32_t swz(uint32_t off) { return off ^ ((off >> 3) & 0x70); }

__device__ __forceinline__ void ldsm4(uint32_t* r, uint32_t addr) {
    asm volatile("ldmatrix.sync.aligned.m8n8.x4.shared.b16 {%0,%1,%2,%3}, [%4];"
        : "=r"(r[0]), "=r"(r[1]), "=r"(r[2]), "=r"(r[3]) : "r"(addr));
}
__device__ __forceinline__ void mma16816(float* c, const uint32_t* a, const uint32_t* b) {
    asm volatile("mma.sync.aligned.m16n8k16.row.col.f32.bf16.bf16.f32 "
        "{%0,%1,%2,%3}, {%4,%5,%6,%7}, {%8,%9}, {%0,%1,%2,%3};"
        : "+f"(c[0]), "+f"(c[1]), "+f"(c[2]), "+f"(c[3])
        : "r"(a[0]), "r"(a[1]), "r"(a[2]), "r"(a[3]), "r"(b[0]), "r"(b[1]));
}

// ---- packed fp32x2 (each lane = IEEE fp32 fma/mul with RN -> bit-identical to scalar) ----
typedef unsigned long long u64;
__device__ __forceinline__ void fma2(u64& d, u64 a, u64 b) {
    asm("fma.rn.f32x2 %0, %1, %2, %3;" : "=l"(d) : "l"(a), "l"(b), "l"(d));
}
__device__ __forceinline__ void mul2(u64& d, u64 a) {
    asm("mul.rn.f32x2 %0, %1, %2;" : "=l"(d) : "l"(d), "l"(a));
}
__device__ __forceinline__ u64 bcast2(float x) {
    u64 r; asm("mov.b64 %0, {%1, %1};" : "=l"(r) : "f"(x)); return r;
}
__device__ __forceinline__ float2 unpk(u64 v) {
    float2 r; asm("mov.b64 {%0, %1}, %2;" : "=f"(r.x), "=f"(r.y) : "l"(v)); return r;
}

// ---------------- prep kernels ----------------
__global__ __launch_bounds__(256) void repack_kernel(
    const float* __restrict__ wq, const float* __restrict__ wk,
    const float* __restrict__ wv, float* __restrict__ W)
{
    int i = blockIdx.x * 256 + threadIdx.x;
    int m = i >> 10, col = i & 1023;
    int src = (((col >> 6) * MDIM + m) << 6) + (col & 63);
    float* dst = W + (size_t)m * 3072 + col;
    dst[0]    = wq[src];
    dst[1024] = wk[src];
    dst[2048] = wv[src];
}

__global__ __launch_bounds__(256) void repack_qk_kernel(
    const float* __restrict__ wq, const float* __restrict__ wk, float* __restrict__ W)
{
    int i = blockIdx.x * 256 + threadIdx.x;
    int m = i >> 10, col = i & 1023;
    int src = (((col >> 6) * MDIM + m) << 6) + (col & 63);
    W[(size_t)m * 2048 + col]        = wq[src];
    W[(size_t)m * 2048 + 1024 + col] = wk[src];
}

__global__ __launch_bounds__(256) void split_kernel(
    const float* __restrict__ in, __nv_bfloat16* __restrict__ hi,
    __nv_bfloat16* __restrict__ lo, int n)
{
    int i = (blockIdx.x * 256 + threadIdx.x) * 4;
    if (i >= n) return;
    float4 v = *(const float4*)(in + i);
    float x[4] = {v.x, v.y, v.z, v.w};
#pragma unroll
    for (int j = 0; j < 4; j++) {
        __nv_bfloat16 h = __float2bfloat16(x[j]);
        hi[i + j] = h;
        lo[i + j] = __float2bfloat16(x[j] - __bfloat162float(h));
    }
}

__global__ void tsplit_kernel(const float* __restrict__ in,
    __nv_bfloat16* __restrict__ hi, __nv_bfloat16* __restrict__ lo, int K, int P)
{
    __shared__ float tile[32][33];
    int p0 = blockIdx.x * 32, k0 = blockIdx.y * 32;
    int tx = threadIdx.x, ty = threadIdx.y;
#pragma unroll
    for (int j = 0; j < 4; j++)
        tile[ty + j * 8][tx] = in[(size_t)(k0 + ty + j * 8) * P + p0 + tx];
    __syncthreads();
#pragma unroll
    for (int j = 0; j < 4; j++) {
        int p = p0 + ty + j * 8, k = k0 + tx;
        float x = tile[tx][ty + j * 8];
        __nv_bfloat16 h = __float2bfloat16(x);
        hi[(size_t)p * K + k] = h;
        lo[(size_t)p * K + k] = __float2bfloat16(x - __bfloat162float(h));
    }
}

__global__ __launch_bounds__(256) void wvsplit_kernel(
    const float* __restrict__ wv, __nv_bfloat16* __restrict__ hi, __nv_bfloat16* __restrict__ lo)
{
    int idx = blockIdx.x * 256 + threadIdx.x;
    int p = idx >> 10, k = idx & 1023;
    float x = wv[(size_t)(((p >> 6) * MDIM + k) << 6) + (p & 63)];
    __nv_bfloat16 h = __float2bfloat16(x);
    hi[idx] = h;
    lo[idx] = __float2bfloat16(x - __bfloat162float(h));
}

// ---------------- 3-pass split-bf16 HMMA GEMM (unchanged from R9/R10) ----------------
#define MMA_STAGE 65536
#define MMA_SMEM  (2*MMA_STAGE + 1024)

__device__ __forceinline__ void stage_load(uint32_t sb,
    const __nv_bfloat16* Ah, const __nv_bfloat16* Al,
    const __nv_bfloat16* Bh, const __nv_bfloat16* Bl,
    int Kdim, int kofs, int rowA, int colB, int t)
{
#pragma unroll
    for (int j = 0; j < 4; j++) {
        int g = j * 256 + t;
        int r = g >> 3, c16 = g & 7;
        uint32_t sw = swz((uint32_t)(r * 128 + c16 * 16));
        size_t ao = (size_t)(rowA + r) * Kdim + kofs + c16 * 8;
        size_t bo = (size_t)(colB + r) * Kdim + kofs + c16 * 8;
        cp16(sb + sw,         Ah + ao);
        cp16(sb + 16384 + sw, Al + ao);
        cp16(sb + 32768 + sw, Bh + bo);
        cp16(sb + 49152 + sw, Bl + bo);
    }
}

__global__ __launch_bounds__(256, 1) void mma_gemm_kernel(
    const __nv_bfloat16* __restrict__ Ah, const __nv_bfloat16* __restrict__ Al,
    const __nv_bfloat16* __restrict__ Bh, const __nv_bfloat16* __restrict__ Bl,
    const float* __restrict__ bias, float* __restrict__ C,
    __nv_bfloat16* __restrict__ outH, __nv_bfloat16* __restrict__ outL,
    int Kdim, int ldc, int relu)
{
    extern __shared__ char dynsm[];
    uint32_t sd = (smem_u32(dynsm) + 1023u) & ~1023u;

    int t = threadIdx.x, wid = t >> 5, lane = t & 31;
    int warp_m = wid & 1, warp_n = wid >> 1;
    int rowA = blockIdx.y * 128, colB = blockIdx.x * 128;

    float acc[4][4][4];
#pragma unroll
    for (int i = 0; i < 4; i++)
#pragma unroll
        for (int j = 0; j < 4; j++)
#pragma unroll
            for (int k = 0; k < 4; k++) acc[i][j][k] = 0.f;

    int rA = lane & 15;
    int cA = (lane >> 4) << 3;
    int rB = (lane & 7) + ((lane >> 4) << 3);
    int cB = lane & 8;

    int nc = Kdim >> 6;
    stage_load(sd, Ah, Al, Bh, Bl, Kdim, 0, rowA, colB, t);
    CP_COMMIT();

    for (int c = 0; c < nc; c++) {
        if (c + 1 < nc) {
            stage_load(sd + ((c + 1) & 1) * MMA_STAGE, Ah, Al, Bh, Bl,
                       Kdim, (c + 1) << 6, rowA, colB, t);
            CP_COMMIT();
            asm volatile("cp.async.wait_group 1;" ::: "memory");
        } else {
            asm volatile("cp.async.wait_group 0;" ::: "memory");
        }
        __syncthreads();
        uint32_t base = sd + (c & 1) * MMA_STAGE;

#pragma unroll
        for (int ks = 0; ks < 4; ks++) {
            int Kc = ks * 16;
            uint32_t aH[4][4], aL[4][4], bH[4][2], bL[4][2];
#pragma unroll
            for (int mt = 0; mt < 4; mt++) {
                uint32_t sw = swz((uint32_t)((warp_m * 64 + mt * 16 + rA) * 128 + (Kc + cA) * 2));
                ldsm4(aH[mt], base + sw);
                ldsm4(aL[mt], base + 16384 + sw);
            }
#pragma unroll
            for (int p = 0; p < 2; p++) {
                uint32_t sw = swz((uint32_t)((warp_n * 32 + p * 16 + rB) * 128 + (Kc + cB) * 2));
                uint32_t q[4];
                ldsm4(q, base + 32768 + sw);
                bH[2*p][0] = q[0]; bH[2*p][1] = q[1]; bH[2*p+1][0] = q[2]; bH[2*p+1][1] = q[3];
                ldsm4(q, base + 49152 + sw);
                bL[2*p][0] = q[0]; bL[2*p][1] = q[1]; bL[2*p+1][0] = q[2]; bL[2*p+1][1] = q[3];
            }
#pragma unroll
            for (int mt = 0; mt < 4; mt++)
#pragma unroll
                for (int nt = 0; nt < 4; nt++) {
                    mma16816(acc[mt][nt], aH[mt], bH[nt]);
                    mma16816(acc[mt][nt], aH[mt], bL[nt]);
                    mma16816(acc[mt][nt], aL[mt], bH[nt]);
                }
        }
        __syncthreads();
    }

    int r0 = rowA + warp_m * 64 + (lane >> 2);
    int c0 = colB + warp_n * 32 + (lane & 3) * 2;
#pragma unroll
    for (int mt = 0; mt < 4; mt++) {
#pragma unroll
        for (int nt = 0; nt < 4; nt++) {
            int col = c0 + nt * 8;
            float bb0 = 0.f, bb1 = 0.f;
            if (bias) { bb0 = bias[col]; bb1 = bias[col + 1]; }
            float v0 = acc[mt][nt][0] + bb0;
            float v1 = acc[mt][nt][1] + bb1;
            float v2 = acc[mt][nt][2] + bb0;
            float v3 = acc[mt][nt][3] + bb1;
            if (relu) {
                v0 = fmaxf(v0, 0.f); v1 = fmaxf(v1, 0.f);
                v2 = fmaxf(v2, 0.f); v3 = fmaxf(v3, 0.f);
            }
            size_t ra = (size_t)(r0 + mt * 16) * ldc + col;
            size_t rb = ra + 8 * (size_t)ldc;
            if (outH) {
                __nv_bfloat162 h, l;
                h.x = __float2bfloat16(v0); h.y = __float2bfloat16(v1);
                l.x = __float2bfloat16(v0 - __bfloat162float(h.x));
                l.y = __float2bfloat16(v1 - __bfloat162float(h.y));
                *(__nv_bfloat162*)&outH[ra] = h;
                *(__nv_bfloat162*)&outL[ra] = l;
                h.x = __float2bfloat16(v2); h.y = __float2bfloat16(v3);
                l.x = __float2bfloat16(v2 - __bfloat162float(h.x));
                l.y = __float2bfloat16(v3 - __bfloat162float(h.y));
                *(__nv_bfloat162*)&outH[rb] = h;
                *(__nv_bfloat162*)&outL[rb] = l;
            } else {
                *(float2*)&C[ra] = make_float2(v0, v1);
                *(float2*)&C[rb] = make_float2(v2, v3);
            }
        }
    }
}

// ---------------- fp32 SGEMM, packed-f32x2 inner loop (bit-identical per element) ----------------
__global__ __launch_bounds__(256) void sgemm_kernel(
    const float* __restrict__ A, const float* __restrict__ B,
    float* __restrict__ C, int Kdim, int lda, int ldb, int ldc)
{
    __shared__ float sA[16][128];
    __shared__ float sB[16][128];

    int t = threadIdx.x;
    int tx = t & 15, ty = t >> 4;
    int rowBase = blockIdx.y * 128, colBase = blockIdx.x * 128;

    u64 acc2[8][4];
#pragma unroll
    for (int i = 0; i < 8; i++)
#pragma unroll
        for (int j = 0; j < 4; j++) acc2[i][j] = 0ull;

    int arow = t >> 1, acol = (t & 1) * 4;
    int brow = t >> 5, bcol = (t & 31) * 4;
    const float* Aptr = A + (size_t)(rowBase + arow) * lda + acol;
    const float* Bptr = B + (size_t)brow * ldb + colBase + bcol;

    for (int kt = 0; kt < Kdim; kt += 16) {
        float4 a0 = *(const float4*)(Aptr);
        float4 a1 = *(const float4*)(Aptr + 8);
        float4 b0 = *(const float4*)(Bptr);
        float4 b1 = *(const float4*)(Bptr + 8 * (size_t)ldb);
        sA[acol+0][arow]=a0.x; sA[acol+1][arow]=a0.y; sA[acol+2][arow]=a0.z; sA[acol+3][arow]=a0.w;
        sA[acol+8][arow]=a1.x; sA[acol+9][arow]=a1.y; sA[acol+10][arow]=a1.z; sA[acol+11][arow]=a1.w;
        *(float4*)&sB[brow][bcol] = b0;
        *(float4*)&sB[brow+8][bcol] = b1;
        __syncthreads();
#pragma unroll
        for (int k = 0; k < 16; k++) {
            float4 x0 = *(const float4*)&sA[k][ty*4];
            float4 x1 = *(const float4*)&sA[k][64+ty*4];
            ulonglong2 yb0 = *(const ulonglong2*)&sB[k][tx*4];       // (b0,b1),(b2,b3)
            ulonglong2 yb1 = *(const ulonglong2*)&sB[k][64+tx*4];    // (b4,b5),(b6,b7)
            float av[8] = {x0.x,x0.y,x0.z,x0.w,x1.x,x1.y,x1.z,x1.w};
#pragma unroll
            for (int i = 0; i < 8; i++) {
                u64 ai = bcast2(av[i]);
                fma2(acc2[i][0], ai, yb0.x);
                fma2(acc2[i][1], ai, yb0.y);
                fma2(acc2[i][2], ai, yb1.x);
                fma2(acc2[i][3], ai, yb1.y);
            }
        }
        __syncthreads();
        Aptr += 16;
        Bptr += 16 * (size_t)ldb;
    }
    int c0 = colBase + tx * 4, c1 = colBase + 64 + tx * 4;
#pragma unroll
    for (int i = 0; i < 8; i++) {
        int r = rowBase + ((i < 4) ? (ty*4+i) : (64+ty*4+i-4));
        float2 p0 = unpk(acc2[i][0]), p1 = unpk(acc2[i][1]);
        float2 p2 = unpk(acc2[i][2]), p3 = unpk(acc2[i][3]);
        *(float4*)&C[(size_t)r*ldc + c0] = make_float4(p0.x, p0.y, p1.x, p1.y);
        *(float4*)&C[(size_t)r*ldc + c1] = make_float4(p2.x, p2.y, p3.x, p3.y);
    }
}

// ---------------- attention (R10 layout; QK/PV packed f32x2, bit-identical math) ----------------
#define QP 68
#define SQT_OFF   0
#define SKT_OFF   4352
#define SP_OFF    8704
#define SKRAW_OFF 13056
#define SV_OFF    17152
#define ATT_SMEM_BYTES ((SV_OFF + 2*4096) * 4)

__global__ __launch_bounds__(256, 2) void attn_kernel(
    const float* __restrict__ Qb, int qs,
    const float* __restrict__ Kb, int ks_,
    const float* __restrict__ Vb, int vs,
    float* __restrict__ AO, int masked)
{
    extern __shared__ float sm[];
    float* sQT   = sm + SQT_OFF;
    float* sKT   = sm + SKT_OFF;
    float* sP    = sm + SP_OFF;
    float* sKraw = sm + SKRAW_OFF;
    uint32_t sbase = smem_u32(sm);
    uint32_t kraw_b = sbase + SKRAW_OFF * 4;
    uint32_t v_b0   = sbase + SV_OFF * 4;

    int t = threadIdx.x;
    int tx = t & 15, ty = t >> 4;
    int tx4 = tx * 4, ty4 = ty * 4;
    int q0 = blockIdx.x * 64;
    int b = blockIdx.y >> 4, h = blockIdx.y & 15;

    const float* qbase = Qb + (size_t)b * CDIM * qs + h * 64;
    const float* kbase = Kb + (size_t)b * CDIM * ks_ + h * 64;
    const float* vbase = Vb + (size_t)b * CDIM * vs + h * 64;

#pragma unroll
    for (int it = 0; it < 4; it++) {
        int idx = it * 256 + t;
        int row = idx >> 4, ch = idx & 15;
        cp16(kraw_b + row * 256 + ch * 16, kbase + (size_t)row * ks_ + ch * 4);
        cp16(v_b0 + row * 256 + ch * 16, vbase + (size_t)row * vs + ch * 4);
    }
    CP_COMMIT();

#pragma unroll
    for (int it = 0; it < 4; it++) {
        int idx = it * 256 + t;
        int qi = idx >> 4, dg = idx & 15;
        float4 v = *(const float4*)&qbase[(size_t)(q0 + qi) * qs + dg * 4];
        sQT[(dg * 4 + 0) * QP + qi] = v.x;
        sQT[(dg * 4 + 1) * QP + qi] = v.y;
        sQT[(dg * 4 + 2) * QP + qi] = v.z;
        sQT[(dg * 4 + 3) * QP + qi] = v.w;
    }

    float m_run[4], l_run[4];
    u64 o2[4][2];
#pragma unroll
    for (int i = 0; i < 4; i++) {
        m_run[i] = -INFINITY; l_run[i] = 0.f;
        o2[i][0] = 0ull; o2[i][1] = 0ull;
    }

    for (int kt = 0; kt < 32; kt++) {
        int cur = kt & 1;
        int k0 = kt * 64;
        asm volatile("cp.async.wait_group 0;" ::: "memory");
        __syncthreads();

#pragma unroll
        for (int it = 0; it < 4; it++) {
            int idx = it * 256 + t;
            int kj = idx >> 4, dg = idx & 15;
            float4 v = *(const float4*)&sKraw[kj * 64 + dg * 4];
            int col = kj ^ ((dg & 7) << 2);
            sKT[(dg * 4 + 0) * QP + col] = v.x;
            sKT[(dg * 4 + 1) * QP + col] = v.y;
            sKT[(dg * 4 + 2) * QP + col] = v.z;
            sKT[(dg * 4 + 3) * QP + col] = v.w;
        }
        __syncthreads();

        if (kt + 1 < 32) {
            int k0n = k0 + 64;
            uint32_t vdst = v_b0 + (cur ^ 1) * 16384;
#pragma unroll
            for (int it = 0; it < 4; it++) {
                int idx = it * 256 + t;
                int row = idx >> 4, ch = idx & 15;
                cp16(kraw_b + row * 256 + ch * 16, kbase + (size_t)(k0n + row) * ks_ + ch * 4);
                cp16(vdst + row * 256 + ch * 16, vbase + (size_t)(k0n + row) * vs + ch * 4);
            }
            CP_COMMIT();
        }

        // ---- S = Q K^T (packed pairs of key-columns; per-lane fma order = R10) ----
        u64 s2[4][2];
#pragma unroll
        for (int i = 0; i < 4; i++) { s2[i][0] = 0ull; s2[i][1] = 0ull; }

#pragma unroll 4
        for (int dg = 0; dg < 16; dg++) {
            int colx = tx4 ^ ((dg & 7) << 2);
#pragma unroll
            for (int e = 0; e < 4; e++) {
                int d = dg * 4 + e;
                float4 a = *(const float4*)&sQT[d * QP + ty4];
                ulonglong2 kp = *(const ulonglong2*)&sKT[d * QP + colx]; // (k0,k1),(k2,k3)
                u64 b0 = bcast2(a.x), b1 = bcast2(a.y);
                u64 b2 = bcast2(a.z), b3 = bcast2(a.w);
                fma2(s2[0][0], b0, kp.x); fma2(s2[0][1], b0, kp.y);
                fma2(s2[1][0], b1, kp.x); fma2(s2[1][1], b1, kp.y);
                fma2(s2[2][0], b2, kp.x); fma2(s2[2][1], b2, kp.y);
                fma2(s2[3][0], b3, kp.x); fma2(s2[3][1], b3, kp.y);
            }
        }

        // ---- mask + scale + online softmax (scalar, identical to R10) ----
#pragma unroll
        for (int i = 0; i < 4; i++) {
            float2 u0 = unpk(s2[i][0]), u1 = unpk(s2[i][1]);
            float s0 = u0.x, s1 = u0.y, sv2 = u1.x, s3 = u1.y;
            int qg = q0 + ty4 + i;
            if (masked) {
                if ((k0 + tx4 + 0) <= qg) s0 -= 100.f;
                if ((k0 + tx4 + 1) <= qg) s1 -= 100.f;
                if ((k0 + tx4 + 2) <= qg) sv2 -= 100.f;
                if ((k0 + tx4 + 3) <= qg) s3 -= 100.f;
            }
            s0 *= 0.125f; s1 *= 0.125f; sv2 *= 0.125f; s3 *= 0.125f;
            float mx = fmaxf(fmaxf(s0, s1), fmaxf(sv2, s3));
#pragma unroll
            for (int off = 8; off >= 1; off >>= 1)
                mx = fmaxf(mx, __shfl_xor_sync(0xffffffffu, mx, off, 16));
            float mnew = fmaxf(m_run[i], mx);
            float p0 = expf(s0 - mnew);
            float p1 = expf(s1 - mnew);
            float p2 = expf(sv2 - mnew);
            float p3 = expf(s3 - mnew);
            float rs = p0 + p1 + p2 + p3;
#pragma unroll
            for (int off = 8; off >= 1; off >>= 1)
                rs += __shfl_xor_sync(0xffffffffu, rs, off, 16);
            float corr = expf(m_run[i] - mnew);
            l_run[i] = l_run[i] * corr + rs;
            m_run[i] = mnew;
            u64 c2 = bcast2(corr);
            mul2(o2[i][0], c2);
            mul2(o2[i][1], c2);
            *(float4*)&sP[(ty4 + i) * QP + tx4] = make_float4(p0, p1, p2, p3);
        }
        __syncthreads();

        // ---- O += P V (packed pairs of v-columns; per-lane fma order = R10) ----
        const float* sVc = sm + SV_OFF + cur * 4096;
#pragma unroll 4
        for (int kj0 = 0; kj0 < 64; kj0 += 4) {
            float4 pa0 = *(const float4*)&sP[(ty4 + 0) * QP + kj0];
            float4 pa1 = *(const float4*)&sP[(ty4 + 1) * QP + kj0];
            float4 pa2 = *(const float4*)&sP[(ty4 + 2) * QP + kj0];
            float4 pa3 = *(const float4*)&sP[(ty4 + 3) * QP + kj0];
#pragma unroll
            for (int e = 0; e < 4; e++) {
                ulonglong2 vp = *(const ulonglong2*)&sVc[(kj0 + e) * 64 + tx4];
                u64 b0 = bcast2(((const float*)&pa0)[e]);
                u64 b1 = bcast2(((const float*)&pa1)[e]);
                u64 b2 = bcast2(((const float*)&pa2)[e]);
                u64 b3 = bcast2(((const float*)&pa3)[e]);
                fma2(o2[0][0], b0, vp.x); fma2(o2[0][1], b0, vp.y);
                fma2(o2[1][0], b1, vp.x); fma2(o2[1][1], b1, vp.y);
                fma2(o2[2][0], b2, vp.x); fma2(o2[2][1], b2, vp.y);
                fma2(o2[3][0], b3, vp.x); fma2(o2[3][1], b3, vp.y);
            }
        }
    }

#pragma unroll
    for (int i = 0; i < 4; i++) {
        float inv = 1.f / l_run[i];
        float2 w0 = unpk(o2[i][0]), w1 = unpk(o2[i][1]);
        size_t row = (size_t)(b * CDIM + q0 + ty4 + i) * MDIM + h * 64 + tx4;
        AO[row + 0] = w0.x * inv;
        AO[row + 1] = w0.y * inv;
        AO[row + 2] = w1.x * inv;
        AO[row + 3] = w1.y * inv;
    }
}

// ---------------- residual add + LayerNorm (unchanged) ----------------
__global__ __launch_bounds__(256) void addln_kernel(
    const float* __restrict__ X, const float* __restrict__ Y,
    const float* __restrict__ g, const float* __restrict__ bta,
    float* __restrict__ out)
{
    __shared__ float red[8];
    int row = blockIdx.x;
    int t = threadIdx.x;
    int lane = t & 31, wid = t >> 5;
    const float* xr = X + (size_t)row * MDIM;
    const float* yr = Y + (size_t)row * MDIM;

    float v[4];
#pragma unroll
    for (int i = 0; i < 4; i++) v[i] = xr[t + 256 * i] + yr[t + 256 * i];

    float s = v[0] + v[1] + v[2] + v[3];
#pragma unroll
    for (int off = 16; off >= 1; off >>= 1) s += __shfl_xor_sync(0xffffffffu, s, off);
    if (lane == 0) red[wid] = s;
    __syncthreads();
    float tot = 0.f;
#pragma unroll
    for (int i = 0; i < 8; i++) tot += red[i];
    float mu = tot * (1.f / 1024.f);
    __syncthreads();

    float q = 0.f;
#pragma unroll
    for (int i = 0; i < 4; i++) { float d = v[i] - mu; q += d * d; }
#pragma unroll
    for (int off = 16; off >= 1; off >>= 1) q += __shfl_xor_sync(0xffffffffu, q, off);
    if (lane == 0) red[wid] = q;
    __syncthreads();
    float qtot = 0.f;
#pragma unroll
    for (int i = 0; i < 8; i++) qtot += red[i];
    float inv = rsqrtf(qtot * (1.f / 1024.f) + LN_EPS);

#pragma unroll
    for (int i = 0; i < 4; i++) {
        int c = t + 256 * i;
        out[(size_t)row * MDIM + c] = (v[i] - mu) * inv * g[c] + bta[c];
    }
}

// ---------------- launcher (R10 topology) ----------------
extern "C" void kernel_launch(void* const* d_in, const int* in_sizes, int n_in,
                              void* d_out, int out_size)
{
    const float* enc = (const float*)d_in[0];
    const float* x   = (const float*)d_in[1];
    const float* wq1 = (const float*)d_in[2];
    const float* wk1 = (const float*)d_in[3];
    const float* wv1 = (const float*)d_in[4];
    const float* wo1 = (const float*)d_in[5];
    const float* g1  = (const float*)d_in[6];
    const float* b1  = (const float*)d_in[7];
    const float* wq2 = (const float*)d_in[8];
    const float* wk2 = (const float*)d_in[9];
    const float* wv2 = (const float*)d_in[10];
    const float* wo2 = (const float*)d_in[11];
    const float* g2  = (const float*)d_in[12];
    const float* b2  = (const float*)d_in[13];
    const float* fw1 = (const float*)d_in[14];
    const float* fb1 = (const float*)d_in[15];
    const float* fw2 = (const float*)d_in[16];
    const float* fb2 = (const float*)d_in[17];
    const float* g3  = (const float*)d_in[18];
    const float* b3  = (const float*)d_in[19];
    float* out = (float*)d_out;

    float *W1, *W2, *QKV, *V, *AO, *T, *N1, *N2;
    __nv_bfloat16 *Ah, *Al, *Bh, *Bl, *Ch, *Cl;
    cudaGetSymbolAddress((void**)&W1, g_W1);
    cudaGetSymbolAddress((void**)&W2, g_W2);
    cudaGetSymbolAddress((void**)&QKV, g_QKV);
    cudaGetSymbolAddress((void**)&V,  g_V);
    cudaGetSymbolAddress((void**)&AO, g_AO);
    cudaGetSymbolAddress((void**)&T,  g_T);
    cudaGetSymbolAddress((void**)&N1, g_N1);
    cudaGetSymbolAddress((void**)&N2, g_N2);
    cudaGetSymbolAddress((void**)&Ah, g_Ah);
    cudaGetSymbolAddress((void**)&Al, g_Al);
    cudaGetSymbolAddress((void**)&Bh, g_Bh);
    cudaGetSymbolAddress((void**)&Bl, g_Bl);
    cudaGetSymbolAddress((void**)&Ch, g_Ch);
    cudaGetSymbolAddress((void**)&Cl, g_Cl);

    cudaFuncSetAttribute(attn_kernel, cudaFuncAttributeMaxDynamicSharedMemorySize, ATT_SMEM_BYTES);
    cudaFuncSetAttribute(mma_gemm_kernel, cudaFuncAttributeMaxDynamicSharedMemorySize, MMA_SMEM);

    dim3 tsb(32, 8);
    const int NM = NTOK * MDIM;

    // weight repacks
    repack_kernel<<<4096, 256>>>(wq1, wk1, wv1, W1);
    repack_qk_kernel<<<4096, 256>>>(wq2, wk2, W2);

    // ---- masked self attention (all fp32 — feeds N1, logit-critical) ----
    sgemm_kernel<<<dim3(24, 32), 256>>>(x, W1, QKV, 1024, 1024, 3072, 3072);
    attn_kernel<<<dim3(32, 32), 256, ATT_SMEM_BYTES>>>(
        QKV, 3072, QKV + 1024, 3072, QKV + 2048, 3072, AO, 1);
    sgemm_kernel<<<dim3(8, 32), 256>>>(AO, wo1, T, 1024, 1024, 1024, 1024);
    addln_kernel<<<4096, 256>>>(x, T, g1, b1, N1);

    // ---- cross attention: Q/K fp32 (logit-critical), V2/wo2 on tensor ----
    sgemm_kernel<<<dim3(8, 32), 256>>>(N1, W2, QKV, 1024, 1024, 2048, 2048);
    sgemm_kernel<<<dim3(8, 32), 256>>>(enc, W2 + 1024, QKV + 1024, 1024, 1024, 2048, 2048);
    wvsplit_kernel<<<4096, 256>>>(wv2, Bh, Bl);
    split_kernel<<<4096, 256>>>(enc, Ah, Al, NM);
    mma_gemm_kernel<<<dim3(8, 32), 256, MMA_SMEM>>>(
        Ah, Al, Bh, Bl, nullptr, V, nullptr, nullptr, 1024, 1024, 0);
    attn_kernel<<<dim3(32, 32), 256, ATT_SMEM_BYTES>>>(
        QKV, 2048, QKV + 1024, 2048, V, 1024, AO, 0);
    tsplit_kernel<<<dim3(32, 32), tsb>>>(wo2, Bh, Bl, 1024, 1024);
    split_kernel<<<4096, 256>>>(AO, Ah, Al, NM);
    mma_gemm_kernel<<<dim3(8, 32), 256, MMA_SMEM>>>(
        Ah, Al, Bh, Bl, nullptr, T, nullptr, nullptr, 1024, 1024, 0);
    addln_kernel<<<4096, 256>>>(N1, T, g2, b2, N2);

    // ---- FFN (tensor; FFN1 writes split bf16 directly) ----
    tsplit_kernel<<<dim3(128, 32), tsb>>>(fw1, Bh, Bl, 1024, 4096);
    split_kernel<<<4096, 256>>>(N2, Ah, Al, NM);
    mma_gemm_kernel<<<dim3(32, 32), 256, MMA_SMEM>>>(
        Ah, Al, Bh, Bl, fb1, nullptr, Ch, Cl, 1024, 4096, 1);
    tsplit_kernel<<<dim3(32, 128), tsb>>>(fw2, Bh, Bl, 4096, 1024);
    mma_gemm_kernel<<<dim3(8, 32), 256, MMA_SMEM>>>(
        Ch, Cl, Bh, Bl, fb2, T, nullptr, nullptr, 4096, 1024, 0);
    addln_kernel<<<4096, 256>>>(N2, T, g3, b3, out);
}

// round 14
// speedup vs baseline: 1.0603x; 1.0167x over previous
#include <cuda_runtime.h>
#include <cuda_bf16.h>
#include <math.h>
#include <stdint.h>

#define BDIM 2
#define CDIM 2048
#define MDIM 1024
#define NTOK (BDIM*CDIM)
#define FDIM 4096
#define LN_EPS 1e-5f

// ---------------- scratch ----------------
__device__ __align__(256) float g_W1[MDIM*3072];
__device__ __align__(256) float g_W2[MDIM*2048];
__device__ __align__(256) float g_QKV[(size_t)NTOK*3072];
__device__ __align__(256) float g_KT[(size_t)32*64*CDIM];   // [b*16+h][d][token]
__device__ __align__(256) float g_V[(size_t)NTOK*MDIM];
__device__ __align__(256) float g_AO[(size_t)NTOK*MDIM];
__device__ __align__(256) float g_T[(size_t)NTOK*MDIM];
__device__ __align__(256) float g_N1[(size_t)NTOK*MDIM];
__device__ __align__(256) float g_N2[(size_t)NTOK*MDIM];
__device__ __align__(256) __nv_bfloat16 g_Ah[(size_t)NTOK*MDIM];
__device__ __align__(256) __nv_bfloat16 g_Al[(size_t)NTOK*MDIM];
__device__ __align__(256) __nv_bfloat16 g_Bh[(size_t)FDIM*MDIM];
__device__ __align__(256) __nv_bfloat16 g_Bl[(size_t)FDIM*MDIM];
__device__ __align__(256) __nv_bfloat16 g_Ch[(size_t)NTOK*FDIM];
__device__ __align__(256) __nv_bfloat16 g_Cl[(size_t)NTOK*FDIM];

// ---------------- helpers ----------------
__device__ __forceinline__ uint32_t smem_u32(const void* p) {
    uint32_t a;
    asm("{ .reg .u64 t; cvta.to.shared.u64 t, %1; cvt.u32.u64 %0, t; }" : "=r"(a) : "l"(p));
    return a;
}
__device__ __forceinline__ void cp16(uint32_t dst, const void* src) {
    asm volatile("cp.async.cg.shared.global [%0], [%1], 16;" :: "r"(dst), "l"(src));
}
#define CP_COMMIT() asm volatile("cp.async.commit_group;" ::: "memory")
__device__ __forceinline__ uint32_t swz(uint32_t off) { return off ^ ((off >> 3) & 0x70); }

__device__ __forceinline__ void ldsm4(uint32_t* r, uint32_t addr) {
    asm volatile("ldmatrix.sync.aligned.m8n8.x4.shared.b16 {%0,%1,%2,%3}, [%4];"
        : "=r"(r[0]), "=r"(r[1]), "=r"(r[2]), "=r"(r[3]) : "r"(addr));
}
__device__ __forceinline__ void mma16816(float* c, const uint32_t* a, const uint32_t* b) {
    asm volatile("mma.sync.aligned.m16n8k16.row.col.f32.bf16.bf16.f32 "
        "{%0,%1,%2,%3}, {%4,%5,%6,%7}, {%8,%9}, {%0,%1,%2,%3};"
        : "+f"(c[0]), "+f"(c[1]), "+f"(c[2]), "+f"(c[3])
        : "r"(a[0]), "r"(a[1]), "r"(a[2]), "r"(a[3]), "r"(b[0]), "r"(b[1]));
}

// ---- packed fp32x2 (each lane = IEEE fp32 fma/mul with RN -> bit-identical to scalar) ----
typedef unsigned long long u64;
__device__ __forceinline__ void fma2(u64& d, u64 a, u64 b) {
    asm("fma.rn.f32x2 %0, %1, %2, %3;" : "=l"(d) : "l"(a), "l"(b), "l"(d));
}
__device__ __forceinline__ void mul2(u64& d, u64 a) {
    asm("mul.rn.f32x2 %0, %1, %2;" : "=l"(d) : "l"(d), "l"(a));
}
__device__ __forceinline__ u64 bcast2(float x) {
    u64 r; asm("mov.b64 %0, {%1, %1};" : "=l"(r) : "f"(x)); return r;
}
__device__ __forceinline__ float2 unpk(u64 v) {
    float2 r; asm("mov.b64 {%0, %1}, %2;" : "=f"(r.x), "=f"(r.y) : "l"(v)); return r;
}

// ---------------- prep kernels ----------------
__global__ __launch_bounds__(256) void repack_kernel(
    const float* __restrict__ wq, const float* __restrict__ wk,
    const float* __restrict__ wv, float* __restrict__ W)
{
    int i = blockIdx.x * 256 + threadIdx.x;
    int m = i >> 10, col = i & 1023;
    int src = (((col >> 6) * MDIM + m) << 6) + (col & 63);
    float* dst = W + (size_t)m * 3072 + col;
    dst[0]    = wq[src];
    dst[1024] = wk[src];
    dst[2048] = wv[src];
}

__global__ __launch_bounds__(256) void repack_qk_kernel(
    const float* __restrict__ wq, const float* __restrict__ wk, float* __restrict__ W)
{
    int i = blockIdx.x * 256 + threadIdx.x;
    int m = i >> 10, col = i & 1023;
    int src = (((col >> 6) * MDIM + m) << 6) + (col & 63);
    W[(size_t)m * 2048 + col]        = wq[src];
    W[(size_t)m * 2048 + 1024 + col] = wk[src];
}

// K slab of QKV -> KT[b*16+h][d][token]  (pure relayout, bit-exact)
__global__ void kt_kernel(const float* __restrict__ src, int stride, float* __restrict__ KT)
{
    __shared__ float tile[32][33];
    int bh = blockIdx.z;
    int b = bh >> 4, h = bh & 15;
    int c0 = blockIdx.x * 32, d0 = blockIdx.y * 32;
    int tx = threadIdx.x, ty = threadIdx.y;
    const float* s = src + (size_t)(b * CDIM) * stride + h * 64;
#pragma unroll
    for (int j = 0; j < 4; j++)
        tile[ty + j * 8][tx] = s[(size_t)(c0 + ty + j * 8) * stride + d0 + tx];
    float* o = KT + (size_t)bh * 64 * CDIM;
    __syncthreads();
#pragma unroll
    for (int j = 0; j < 4; j++)
        o[(size_t)(d0 + ty + j * 8) * CDIM + c0 + tx] = tile[tx][ty + j * 8];
}

__global__ __launch_bounds__(256) void split_kernel(
    const float* __restrict__ in, __nv_bfloat16* __restrict__ hi,
    __nv_bfloat16* __restrict__ lo, int n)
{
    int i = (blockIdx.x * 256 + threadIdx.x) * 4;
    if (i >= n) return;
    float4 v = *(const float4*)(in + i);
    float x[4] = {v.x, v.y, v.z, v.w};
#pragma unroll
    for (int j = 0; j < 4; j++) {
        __nv_bfloat16 h = __float2bfloat16(x[j]);
        hi[i + j] = h;
        lo[i + j] = __float2bfloat16(x[j] - __bfloat162float(h));
    }
}

__global__ void tsplit_kernel(const float* __restrict__ in,
    __nv_bfloat16* __restrict__ hi, __nv_bfloat16* __restrict__ lo, int K, int P)
{
    __shared__ float tile[32][33];
    int p0 = blockIdx.x * 32, k0 = blockIdx.y * 32;
    int tx = threadIdx.x, ty = threadIdx.y;
#pragma unroll
    for (int j = 0; j < 4; j++)
        tile[ty + j * 8][tx] = in[(size_t)(k0 + ty + j * 8) * P + p0 + tx];
    __syncthreads();
#pragma unroll
    for (int j = 0; j < 4; j++) {
        int p = p0 + ty + j * 8, k = k0 + tx;
        float x = tile[tx][ty + j * 8];
        __nv_bfloat16 h = __float2bfloat16(x);
        hi[(size_t)p * K + k] = h;
        lo[(size_t)p * K + k] = __float2bfloat16(x - __bfloat162float(h));
    }
}

__global__ __launch_bounds__(256) void wvsplit_kernel(
    const float* __restrict__ wv, __nv_bfloat16* __restrict__ hi, __nv_bfloat16* __restrict__ lo)
{
    int idx = blockIdx.x * 256 + threadIdx.x;
    int p = idx >> 10, k = idx & 1023;
    float x = wv[(size_t)(((p >> 6) * MDIM + k) << 6) + (p & 63)];
    __nv_bfloat16 h = __float2bfloat16(x);
    hi[idx] = h;
    lo[idx] = __float2bfloat16(x - __bfloat162float(h));
}

// ---------------- 3-pass split-bf16 HMMA GEMM (unchanged) ----------------
#define MMA_STAGE 65536
#define MMA_SMEM  (2*MMA_STAGE + 1024)

__device__ __forceinline__ void stage_load(uint32_t sb,
    const __nv_bfloat16* Ah, const __nv_bfloat16* Al,
    const __nv_bfloat16* Bh, const __nv_bfloat16* Bl,
    int Kdim, int kofs, int rowA, int colB, int t)
{
#pragma unroll
    for (int j = 0; j < 4; j++) {
        int g = j * 256 + t;
        int r = g >> 3, c16 = g & 7;
        uint32_t sw = swz((uint32_t)(r * 128 + c16 * 16));
        size_t ao = (size_t)(rowA + r) * Kdim + kofs + c16 * 8;
        size_t bo = (size_t)(colB + r) * Kdim + kofs + c16 * 8;
        cp16(sb + sw,         Ah + ao);
        cp16(sb + 16384 + sw, Al + ao);
        cp16(sb + 32768 + sw, Bh + bo);
        cp16(sb + 49152 + sw, Bl + bo);
    }
}

__global__ __launch_bounds__(256, 1) void mma_gemm_kernel(
    const __nv_bfloat16* __restrict__ Ah, const __nv_bfloat16* __restrict__ Al,
    const __nv_bfloat16* __restrict__ Bh, const __nv_bfloat16* __restrict__ Bl,
    const float* __restrict__ bias, float* __restrict__ C,
    __nv_bfloat16* __restrict__ outH, __nv_bfloat16* __restrict__ outL,
    int Kdim, int ldc, int relu)
{
    extern __shared__ char dynsm[];
    uint32_t sd = (smem_u32(dynsm) + 1023u) & ~1023u;

    int t = threadIdx.x, wid = t >> 5, lane = t & 31;
    int warp_m = wid & 1, warp_n = wid >> 1;
    int rowA = blockIdx.y * 128, colB = blockIdx.x * 128;

    float acc[4][4][4];
#pragma unroll
    for (int i = 0; i < 4; i++)
#pragma unroll
        for (int j = 0; j < 4; j++)
#pragma unroll
            for (int k = 0; k < 4; k++) acc[i][j][k] = 0.f;

    int rA = lane & 15;
    int cA = (lane >> 4) << 3;
    int rB = (lane & 7) + ((lane >> 4) << 3);
    int cB = lane & 8;

    int nc = Kdim >> 6;
    stage_load(sd, Ah, Al, Bh, Bl, Kdim, 0, rowA, colB, t);
    CP_COMMIT();

    for (int c = 0; c < nc; c++) {
        if (c + 1 < nc) {
            stage_load(sd + ((c + 1) & 1) * MMA_STAGE, Ah, Al, Bh, Bl,
                       Kdim, (c + 1) << 6, rowA, colB, t);
            CP_COMMIT();
            asm volatile("cp.async.wait_group 1;" ::: "memory");
        } else {
            asm volatile("cp.async.wait_group 0;" ::: "memory");
        }
        __syncthreads();
        uint32_t base = sd + (c & 1) * MMA_STAGE;

#pragma unroll
        for (int ks = 0; ks < 4; ks++) {
            int Kc = ks * 16;
            uint32_t aH[4][4], aL[4][4], bH[4][2], bL[4][2];
#pragma unroll
            for (int mt = 0; mt < 4; mt++) {
                uint32_t sw = swz((uint32_t)((warp_m * 64 + mt * 16 + rA) * 128 + (Kc + cA) * 2));
                ldsm4(aH[mt], base + sw);
                ldsm4(aL[mt], base + 16384 + sw);
            }
#pragma unroll
            for (int p = 0; p < 2; p++) {
                uint32_t sw = swz((uint32_t)((warp_n * 32 + p * 16 + rB) * 128 + (Kc + cB) * 2));
                uint32_t q[4];
                ldsm4(q, base + 32768 + sw);
                bH[2*p][0] = q[0]; bH[2*p][1] = q[1]; bH[2*p+1][0] = q[2]; bH[2*p+1][1] = q[3];
                ldsm4(q, base + 49152 + sw);
                bL[2*p][0] = q[0]; bL[2*p][1] = q[1]; bL[2*p+1][0] = q[2]; bL[2*p+1][1] = q[3];
            }
#pragma unroll
            for (int mt = 0; mt < 4; mt++)
#pragma unroll
                for (int nt = 0; nt < 4; nt++) {
                    mma16816(acc[mt][nt], aH[mt], bH[nt]);
                    mma16816(acc[mt][nt], aH[mt], bL[nt]);
                    mma16816(acc[mt][nt], aL[mt], bH[nt]);
                }
        }
        __syncthreads();
    }

    int r0 = rowA + warp_m * 64 + (lane >> 2);
    int c0 = colB + warp_n * 32 + (lane & 3) * 2;
#pragma unroll
    for (int mt = 0; mt < 4; mt++) {
#pragma unroll
        for (int nt = 0; nt < 4; nt++) {
            int col = c0 + nt * 8;
            float bb0 = 0.f, bb1 = 0.f;
            if (bias) { bb0 = bias[col]; bb1 = bias[col + 1]; }
            float v0 = acc[mt][nt][0] + bb0;
            float v1 = acc[mt][nt][1] + bb1;
            float v2 = acc[mt][nt][2] + bb0;
            float v3 = acc[mt][nt][3] + bb1;
            if (relu) {
                v0 = fmaxf(v0, 0.f); v1 = fmaxf(v1, 0.f);
                v2 = fmaxf(v2, 0.f); v3 = fmaxf(v3, 0.f);
            }
            size_t ra = (size_t)(r0 + mt * 16) * ldc + col;
            size_t rb = ra + 8 * (size_t)ldc;
            if (outH) {
                __nv_bfloat162 h, l;
                h.x = __float2bfloat16(v0); h.y = __float2bfloat16(v1);
                l.x = __float2bfloat16(v0 - __bfloat162float(h.x));
                l.y = __float2bfloat16(v1 - __bfloat162float(h.y));
                *(__nv_bfloat162*)&outH[ra] = h;
                *(__nv_bfloat162*)&outL[ra] = l;
                h.x = __float2bfloat16(v2); h.y = __float2bfloat16(v3);
                l.x = __float2bfloat16(v2 - __bfloat162float(h.x));
                l.y = __float2bfloat16(v3 - __bfloat162float(h.y));
                *(__nv_bfloat162*)&outH[rb] = h;
                *(__nv_bfloat162*)&outL[rb] = l;
            } else {
                *(float2*)&C[ra] = make_float2(v0, v1);
                *(float2*)&C[rb] = make_float2(v2, v3);
            }
        }
    }
}

// ---------------- fp32 SGEMM, packed-f32x2 inner loop (bit-identical per element) ----------------
__global__ __launch_bounds__(256) void sgemm_kernel(
    const float* __restrict__ A, const float* __restrict__ B,
    float* __restrict__ C, int Kdim, int lda, int ldb, int ldc)
{
    __shared__ float sA[16][128];
    __shared__ float sB[16][128];

    int t = threadIdx.x;
    int tx = t & 15, ty = t >> 4;
    int rowBase = blockIdx.y * 128, colBase = blockIdx.x * 128;

    u64 acc2[8][4];
#pragma unroll
    for (int i = 0; i < 8; i++)
#pragma unroll
        for (int j = 0; j < 4; j++) acc2[i][j] = 0ull;

    int arow = t >> 1, acol = (t & 1) * 4;
    int brow = t >> 5, bcol = (t & 31) * 4;
    const float* Aptr = A + (size_t)(rowBase + arow) * lda + acol;
    const float* Bptr = B + (size_t)brow * ldb + colBase + bcol;

    for (int kt = 0; kt < Kdim; kt += 16) {
        float4 a0 = *(const float4*)(Aptr);
        float4 a1 = *(const float4*)(Aptr + 8);
        float4 b0 = *(const float4*)(Bptr);
        float4 b1 = *(const float4*)(Bptr + 8 * (size_t)ldb);
        sA[acol+0][arow]=a0.x; sA[acol+1][arow]=a0.y; sA[acol+2][arow]=a0.z; sA[acol+3][arow]=a0.w;
        sA[acol+8][arow]=a1.x; sA[acol+9][arow]=a1.y; sA[acol+10][arow]=a1.z; sA[acol+11][arow]=a1.w;
        *(float4*)&sB[brow][bcol] = b0;
        *(float4*)&sB[brow+8][bcol] = b1;
        __syncthreads();
#pragma unroll
        for (int k = 0; k < 16; k++) {
            float4 x0 = *(const float4*)&sA[k][ty*4];
            float4 x1 = *(const float4*)&sA[k][64+ty*4];
            ulonglong2 yb0 = *(const ulonglong2*)&sB[k][tx*4];
            ulonglong2 yb1 = *(const ulonglong2*)&sB[k][64+tx*4];
            float av[8] = {x0.x,x0.y,x0.z,x0.w,x1.x,x1.y,x1.z,x1.w};
#pragma unroll
            for (int i = 0; i < 8; i++) {
                u64 ai = bcast2(av[i]);
                fma2(acc2[i][0], ai, yb0.x);
                fma2(acc2[i][1], ai, yb0.y);
                fma2(acc2[i][2], ai, yb1.x);
                fma2(acc2[i][3], ai, yb1.y);
            }
        }
        __syncthreads();
        Aptr += 16;
        Bptr += 16 * (size_t)ldb;
    }
    int c0 = colBase + tx * 4, c1 = colBase + 64 + tx * 4;
#pragma unroll
    for (int i = 0; i < 8; i++) {
        int r = rowBase + ((i < 4) ? (ty*4+i) : (64+ty*4+i-4));
        float2 p0 = unpk(acc2[i][0]), p1 = unpk(acc2[i][1]);
        float2 p2 = unpk(acc2[i][2]), p3 = unpk(acc2[i][3]);
        *(float4*)&C[(size_t)r*ldc + c0] = make_float4(p0.x, p0.y, p1.x, p1.y);
        *(float4*)&C[(size_t)r*ldc + c1] = make_float4(p2.x, p2.y, p3.x, p3.y);
    }
}

// ---------------- attention v4: K pre-transposed in GMEM; cp.async lands swizzled ----------------
// Math (fma order, softmax, mask, swizzled read addresses) bit-identical to R13.
#define QP 68
#define SQT_OFF   0
#define SKT_OFF   4352
#define SP_OFF    13056
#define SV_OFF    17408
#define ATT_SMEM_BYTES ((SV_OFF + 2*4096) * 4)   // 102400 B

__global__ __launch_bounds__(256, 2) void attn_kernel(
    const float* __restrict__ Qb, int qs,
    const float* __restrict__ KTb,            // [b*16+h][64][2048]
    const float* __restrict__ Vb, int vs,
    float* __restrict__ AO, int masked)
{
    extern __shared__ float sm[];
    float* sQT = sm + SQT_OFF;
    float* sP  = sm + SP_OFF;
    uint32_t sbase = smem_u32(sm);
    uint32_t kt_b = sbase + SKT_OFF * 4;
    uint32_t v_b0 = sbase + SV_OFF * 4;

    int t = threadIdx.x;
    int tx = t & 15, ty = t >> 4;
    int tx4 = tx * 4, ty4 = ty * 4;
    int q0 = blockIdx.x * 64;
    int b = blockIdx.y >> 4, h = blockIdx.y & 15;

    const float* qbase  = Qb + (size_t)b * CDIM * qs + h * 64;
    const float* ktbase = KTb + (size_t)blockIdx.y * 64 * CDIM;
    const float* vbase  = Vb + (size_t)b * CDIM * vs + h * 64;

    // prefetch tile 0: K^T rows (swizzled chunks) + V rows
#pragma unroll
    for (int it = 0; it < 4; it++) {
        int idx = it * 256 + t;
        int r = idx >> 4, ch = idx & 15;
        uint32_t kdst = kt_b + (uint32_t)(r * QP * 4 + ((ch ^ ((r >> 2) & 7)) * 16));
        cp16(kdst, ktbase + (size_t)r * CDIM + ch * 4);
        cp16(v_b0 + r * 256 + ch * 16, vbase + (size_t)r * vs + ch * 4);
    }
    CP_COMMIT();

    // load Q transposed (d-major)
#pragma unroll
    for (int it = 0; it < 4; it++) {
        int idx = it * 256 + t;
        int qi = idx >> 4, dg = idx & 15;
        float4 v = *(const float4*)&qbase[(size_t)(q0 + qi) * qs + dg * 4];
        sQT[(dg * 4 + 0) * QP + qi] = v.x;
        sQT[(dg * 4 + 1) * QP + qi] = v.y;
        sQT[(dg * 4 + 2) * QP + qi] = v.z;
        sQT[(dg * 4 + 3) * QP + qi] = v.w;
    }

    float m_run[4], l_run[4];
    u64 o2[4][2];
#pragma unroll
    for (int i = 0; i < 4; i++) {
        m_run[i] = -INFINITY; l_run[i] = 0.f;
        o2[i][0] = 0ull; o2[i][1] = 0ull;
    }

    for (int kt = 0; kt < 32; kt++) {
        int cur = kt & 1;
        int k0 = kt * 64;
        asm volatile("cp.async.wait_group 0;" ::: "memory");
        __syncthreads();   // cur K/V visible; prior iter's reads of alt finished

        // prefetch next tile into alternate buffers
        if (kt + 1 < 32) {
            int k0n = k0 + 64;
            uint32_t kdstb = kt_b + (cur ^ 1) * 4352 * 4;
            uint32_t vdst  = v_b0 + (cur ^ 1) * 16384;
#pragma unroll
            for (int it = 0; it < 4; it++) {
                int idx = it * 256 + t;
                int r = idx >> 4, ch = idx & 15;
                uint32_t kdst = kdstb + (uint32_t)(r * QP * 4 + ((ch ^ ((r >> 2) & 7)) * 16));
                cp16(kdst, ktbase + (size_t)r * CDIM + k0n + ch * 4);
                cp16(vdst + r * 256 + ch * 16, vbase + (size_t)(k0n + r) * vs + ch * 4);
            }
            CP_COMMIT();
        }

        const float* sKT = sm + SKT_OFF + cur * 4352;

        // ---- S = Q K^T (packed; per-lane fma order identical) ----
        u64 s2[4][2];
#pragma unroll
        for (int i = 0; i < 4; i++) { s2[i][0] = 0ull; s2[i][1] = 0ull; }

#pragma unroll 4
        for (int dg = 0; dg < 16; dg++) {
            int colx = tx4 ^ ((dg & 7) << 2);
#pragma unroll
            for (int e = 0; e < 4; e++) {
                int d = dg * 4 + e;
                float4 a = *(const float4*)&sQT[d * QP + ty4];
                ulonglong2 kp = *(const ulonglong2*)&sKT[d * QP + colx];
                u64 b0 = bcast2(a.x), b1 = bcast2(a.y);
                u64 b2 = bcast2(a.z), b3 = bcast2(a.w);
                fma2(s2[0][0], b0, kp.x); fma2(s2[0][1], b0, kp.y);
                fma2(s2[1][0], b1, kp.x); fma2(s2[1][1], b1, kp.y);
                fma2(s2[2][0], b2, kp.x); fma2(s2[2][1], b2, kp.y);
                fma2(s2[3][0], b3, kp.x); fma2(s2[3][1], b3, kp.y);
            }
        }

        // ---- mask + scale + online softmax (identical) ----
#pragma unroll
        for (int i = 0; i < 4; i++) {
            float2 u0 = unpk(s2[i][0]), u1 = unpk(s2[i][1]);
            float s0 = u0.x, s1 = u0.y, sv2 = u1.x, s3 = u1.y;
            int qg = q0 + ty4 + i;
            if (masked) {
                if ((k0 + tx4 + 0) <= qg) s0 -= 100.f;
                if ((k0 + tx4 + 1) <= qg) s1 -= 100.f;
                if ((k0 + tx4 + 2) <= qg) sv2 -= 100.f;
                if ((k0 + tx4 + 3) <= qg) s3 -= 100.f;
            }
            s0 *= 0.125f; s1 *= 0.125f; sv2 *= 0.125f; s3 *= 0.125f;
            float mx = fmaxf(fmaxf(s0, s1), fmaxf(sv2, s3));
#pragma unroll
            for (int off = 8; off >= 1; off >>= 1)
                mx = fmaxf(mx, __shfl_xor_sync(0xffffffffu, mx, off, 16));
            float mnew = fmaxf(m_run[i], mx);
            float p0 = expf(s0 - mnew);
            float p1 = expf(s1 - mnew);
            float p2 = expf(sv2 - mnew);
            float p3 = expf(s3 - mnew);
            float rs = p0 + p1 + p2 + p3;
#pragma unroll
            for (int off = 8; off >= 1; off >>= 1)
                rs += __shfl_xor_sync(0xffffffffu, rs, off, 16);
            float corr = expf(m_run[i] - mnew);
            l_run[i] = l_run[i] * corr + rs;
            m_run[i] = mnew;
            u64 c2 = bcast2(corr);
            mul2(o2[i][0], c2);
            mul2(o2[i][1], c2);
            *(float4*)&sP[(ty4 + i) * QP + tx4] = make_float4(p0, p1, p2, p3);
        }
        __syncthreads();

        // ---- O += P V (packed; per-lane fma order identical) ----
        const float* sVc = sm + SV_OFF + cur * 4096;
#pragma unroll 4
        for (int kj0 = 0; kj0 < 64; kj0 += 4) {
            float4 pa0 = *(const float4*)&sP[(ty4 + 0) * QP + kj0];
            float4 pa1 = *(const float4*)&sP[(ty4 + 1) * QP + kj0];
            float4 pa2 = *(const float4*)&sP[(ty4 + 2) * QP + kj0];
            float4 pa3 = *(const float4*)&sP[(ty4 + 3) * QP + kj0];
#pragma unroll
            for (int e = 0; e < 4; e++) {
                ulonglong2 vp = *(const ulonglong2*)&sVc[(kj0 + e) * 64 + tx4];
                u64 b0 = bcast2(((const float*)&pa0)[e]);
                u64 b1 = bcast2(((const float*)&pa1)[e]);
                u64 b2 = bcast2(((const float*)&pa2)[e]);
                u64 b3 = bcast2(((const float*)&pa3)[e]);
                fma2(o2[0][0], b0, vp.x); fma2(o2[0][1], b0, vp.y);
                fma2(o2[1][0], b1, vp.x); fma2(o2[1][1], b1, vp.y);
                fma2(o2[2][0], b2, vp.x); fma2(o2[2][1], b2, vp.y);
                fma2(o2[3][0], b3, vp.x); fma2(o2[3][1], b3, vp.y);
            }
        }
    }

#pragma unroll
    for (int i = 0; i < 4; i++) {
        float inv = 1.f / l_run[i];
        float2 w0 = unpk(o2[i][0]), w1 = unpk(o2[i][1]);
        size_t row = (size_t)(b * CDIM + q0 + ty4 + i) * MDIM + h * 64 + tx4;
        AO[row + 0] = w0.x * inv;
        AO[row + 1] = w0.y * inv;
        AO[row + 2] = w1.x * inv;
        AO[row + 3] = w1.y * inv;
    }
}

// ---------------- residual add + LayerNorm (unchanged) ----------------
__global__ __launch_bounds__(256) void addln_kernel(
    const float* __restrict__ X, const float* __restrict__ Y,
    const float* __restrict__ g, const float* __restrict__ bta,
    float* __restrict__ out)
{
    __shared__ float red[8];
    int row = blockIdx.x;
    int t = threadIdx.x;
    int lane = t & 31, wid = t >> 5;
    const float* xr = X + (size_t)row * MDIM;
    const float* yr = Y + (size_t)row * MDIM;

    float v[4];
#pragma unroll
    for (int i = 0; i < 4; i++) v[i] = xr[t + 256 * i] + yr[t + 256 * i];

    float s = v[0] + v[1] + v[2] + v[3];
#pragma unroll
    for (int off = 16; off >= 1; off >>= 1) s += __shfl_xor_sync(0xffffffffu, s, off);
    if (lane == 0) red[wid] = s;
    __syncthreads();
    float tot = 0.f;
#pragma unroll
    for (int i = 0; i < 8; i++) tot += red[i];
    float mu = tot * (1.f / 1024.f);
    __syncthreads();

    float q = 0.f;
#pragma unroll
    for (int i = 0; i < 4; i++) { float d = v[i] - mu; q += d * d; }
#pragma unroll
    for (int off = 16; off >= 1; off >>= 1) q += __shfl_xor_sync(0xffffffffu, q, off);
    if (lane == 0) red[wid] = q;
    __syncthreads();
    float qtot = 0.f;
#pragma unroll
    for (int i = 0; i < 8; i++) qtot += red[i];
    float inv = rsqrtf(qtot * (1.f / 1024.f) + LN_EPS);

#pragma unroll
    for (int i = 0; i < 4; i++) {
        int c = t + 256 * i;
        out[(size_t)row * MDIM + c] = (v[i] - mu) * inv * g[c] + bta[c];
    }
}

// ---------------- launcher ----------------
extern "C" void kernel_launch(void* const* d_in, const int* in_sizes, int n_in,
                              void* d_out, int out_size)
{
    const float* enc = (const float*)d_in[0];
    const float* x   = (const float*)d_in[1];
    const float* wq1 = (const float*)d_in[2];
    const float* wk1 = (const float*)d_in[3];
    const float* wv1 = (const float*)d_in[4];
    const float* wo1 = (const float*)d_in[5];
    const float* g1  = (const float*)d_in[6];
    const float* b1  = (const float*)d_in[7];
    const float* wq2 = (const float*)d_in[8];
    const float* wk2 = (const float*)d_in[9];
    const float* wv2 = (const float*)d_in[10];
    const float* wo2 = (const float*)d_in[11];
    const float* g2  = (const float*)d_in[12];
    const float* b2  = (const float*)d_in[13];
    const float* fw1 = (const float*)d_in[14];
    const float* fb1 = (const float*)d_in[15];
    const float* fw2 = (const float*)d_in[16];
    const float* fb2 = (const float*)d_in[17];
    const float* g3  = (const float*)d_in[18];
    const float* b3  = (const float*)d_in[19];
    float* out = (float*)d_out;

    float *W1, *W2, *QKV, *KT, *V, *AO, *T, *N1, *N2;
    __nv_bfloat16 *Ah, *Al, *Bh, *Bl, *Ch, *Cl;
    cudaGetSymbolAddress((void**)&W1, g_W1);
    cudaGetSymbolAddress((void**)&W2, g_W2);
    cudaGetSymbolAddress((void**)&QKV, g_QKV);
    cudaGetSymbolAddress((void**)&KT, g_KT);
    cudaGetSymbolAddress((void**)&V,  g_V);
    cudaGetSymbolAddress((void**)&AO, g_AO);
    cudaGetSymbolAddress((void**)&T,  g_T);
    cudaGetSymbolAddress((void**)&N1, g_N1);
    cudaGetSymbolAddress((void**)&N2, g_N2);
    cudaGetSymbolAddress((void**)&Ah, g_Ah);
    cudaGetSymbolAddress((void**)&Al, g_Al);
    cudaGetSymbolAddress((void**)&Bh, g_Bh);
    cudaGetSymbolAddress((void**)&Bl, g_Bl);
    cudaGetSymbolAddress((void**)&Ch, g_Ch);
    cudaGetSymbolAddress((void**)&Cl, g_Cl);

    cudaFuncSetAttribute(attn_kernel, cudaFuncAttributeMaxDynamicSharedMemorySize, ATT_SMEM_BYTES);
    cudaFuncSetAttribute(mma_gemm_kernel, cudaFuncAttributeMaxDynamicSharedMemorySize, MMA_SMEM);

    dim3 tsb(32, 8);
    dim3 ktg(64, 2, 32);
    const int NM = NTOK * MDIM;

    // weight repacks
    repack_kernel<<<4096, 256>>>(wq1, wk1, wv1, W1);
    repack_qk_kernel<<<4096, 256>>>(wq2, wk2, W2);

    // ---- masked self attention (all fp32 — feeds N1, logit-critical) ----
    sgemm_kernel<<<dim3(24, 32), 256>>>(x, W1, QKV, 1024, 1024, 3072, 3072);
    kt_kernel<<<ktg, tsb>>>(QKV + 1024, 3072, KT);
    attn_kernel<<<dim3(32, 32), 256, ATT_SMEM_BYTES>>>(
        QKV, 3072, KT, QKV + 2048, 3072, AO, 1);
    sgemm_kernel<<<dim3(8, 32), 256>>>(AO, wo1, T, 1024, 1024, 1024, 1024);
    addln_kernel<<<4096, 256>>>(x, T, g1, b1, N1);

    // ---- cross attention: Q/K fp32 (logit-critical), V2/wo2 on tensor ----
    sgemm_kernel<<<dim3(8, 32), 256>>>(N1, W2, QKV, 1024, 1024, 2048, 2048);
    sgemm_kernel<<<dim3(8, 32), 256>>>(enc, W2 + 1024, QKV + 1024, 1024, 1024, 2048, 2048);
    kt_kernel<<<ktg, tsb>>>(QKV + 1024, 2048, KT);
    wvsplit_kernel<<<4096, 256>>>(wv2, Bh, Bl);
    split_kernel<<<4096, 256>>>(enc, Ah, Al, NM);
    mma_gemm_kernel<<<dim3(8, 32), 256, MMA_SMEM>>>(
        Ah, Al, Bh, Bl, nullptr, V, nullptr, nullptr, 1024, 1024, 0);
    attn_kernel<<<dim3(32, 32), 256, ATT_SMEM_BYTES>>>(
        QKV, 2048, KT, V, 1024, AO, 0);
    tsplit_kernel<<<dim3(32, 32), tsb>>>(wo2, Bh, Bl, 1024, 1024);
    split_kernel<<<4096, 256>>>(AO, Ah, Al, NM);
    mma_gemm_kernel<<<dim3(8, 32), 256, MMA_SMEM>>>(
        Ah, Al, Bh, Bl, nullptr, T, nullptr, nullptr, 1024, 1024, 0);
    addln_kernel<<<4096, 256>>>(N1, T, g2, b2, N2);

    // ---- FFN (tensor; FFN1 writes split bf16 directly) ----
    tsplit_kernel<<<dim3(128, 32), tsb>>>(fw1, Bh, Bl, 1024, 4096);
    split_kernel<<<4096, 256>>>(N2, Ah, Al, NM);
    mma_gemm_kernel<<<dim3(32, 32), 256, MMA_SMEM>>>(
        Ah, Al, Bh, Bl, fb1, nullptr, Ch, Cl, 1024, 4096, 1);
    tsplit_kernel<<<dim3(32, 128), tsb>>>(fw2, Bh, Bl, 4096, 1024);
    mma_gemm_kernel<<<dim3(8, 32), 256, MMA_SMEM>>>(
        Ch, Cl, Bh, Bl, fb2, T, nullptr, nullptr, 4096, 1024, 0);
    addln_kernel<<<4096, 256>>>(N2, T, g3, b3, out);
}

// round 15
// speedup vs baseline: 1.0926x; 1.0305x over previous
#include <cuda_runtime.h>
#include <cuda_bf16.h>
#include <math.h>
#include <stdint.h>

#define BDIM 2
#define CDIM 2048
#define MDIM 1024
#define NTOK (BDIM*CDIM)
#define FDIM 4096
#define LN_EPS 1e-5f

// ---------------- scratch ----------------
__device__ __align__(256) float g_W1[MDIM*3072];
__device__ __align__(256) float g_W2[MDIM*2048];
__device__ __align__(256) float g_QKV[(size_t)NTOK*3072];
__device__ __align__(256) float g_KT[(size_t)32*64*CDIM];   // [b*16+h][d][token]
__device__ __align__(256) float g_V[(size_t)NTOK*MDIM];
__device__ __align__(256) float g_AO[(size_t)NTOK*MDIM];
__device__ __align__(256) float g_T[(size_t)NTOK*MDIM];
__device__ __align__(256) float g_N1[(size_t)NTOK*MDIM];
__device__ __align__(256) float g_N2[(size_t)NTOK*MDIM];
__device__ __align__(256) __nv_bfloat16 g_Ah[(size_t)NTOK*MDIM];
__device__ __align__(256) __nv_bfloat16 g_Al[(size_t)NTOK*MDIM];
__device__ __align__(256) __nv_bfloat16 g_Wvh[(size_t)MDIM*MDIM];
__device__ __align__(256) __nv_bfloat16 g_Wvl[(size_t)MDIM*MDIM];
__device__ __align__(256) __nv_bfloat16 g_Wo2h[(size_t)MDIM*MDIM];
__device__ __align__(256) __nv_bfloat16 g_Wo2l[(size_t)MDIM*MDIM];
__device__ __align__(256) __nv_bfloat16 g_F1h[(size_t)FDIM*MDIM];
__device__ __align__(256) __nv_bfloat16 g_F1l[(size_t)FDIM*MDIM];
__device__ __align__(256) __nv_bfloat16 g_F2h[(size_t)FDIM*MDIM];
__device__ __align__(256) __nv_bfloat16 g_F2l[(size_t)FDIM*MDIM];
__device__ __align__(256) __nv_bfloat16 g_Ch[(size_t)NTOK*FDIM];
__device__ __align__(256) __nv_bfloat16 g_Cl[(size_t)NTOK*FDIM];

// ---------------- helpers ----------------
__device__ __forceinline__ uint32_t smem_u32(const void* p) {
    uint32_t a;
    asm("{ .reg .u64 t; cvta.to.shared.u64 t, %1; cvt.u32.u64 %0, t; }" : "=r"(a) : "l"(p));
    return a;
}
__device__ __forceinline__ void cp16(uint32_t dst, const void* src) {
    asm volatile("cp.async.cg.shared.global [%0], [%1], 16;" :: "r"(dst), "l"(src));
}
#define CP_COMMIT() asm volatile("cp.async.commit_group;" ::: "memory")
__device__ __forceinline__ uint32_t swz(uint32_t off) { return off ^ ((off >> 3) & 0x70); }

__device__ __forceinline__ void ldsm4(uint32_t* r, uint32_t addr) {
    asm volatile("ldmatrix.sync.aligned.m8n8.x4.shared.b16 {%0,%1,%2,%3}, [%4];"
        : "=r"(r[0]), "=r"(r[1]), "=r"(r[2]), "=r"(r[3]) : "r"(addr));
}
__device__ __forceinline__ void mma16816(float* c, const uint32_t* a, const uint32_t* b) {
    asm volatile("mma.sync.aligned.m16n8k16.row.col.f32.bf16.bf16.f32 "
        "{%0,%1,%2,%3}, {%4,%5,%6,%7}, {%8,%9}, {%0,%1,%2,%3};"
        : "+f"(c[0]), "+f"(c[1]), "+f"(c[2]), "+f"(c[3])
        : "r"(a[0]), "r"(a[1]), "r"(a[2]), "r"(a[3]), "r"(b[0]), "r"(b[1]));
}

// ---- packed fp32x2 (each lane = IEEE fp32 fma/mul with RN -> bit-identical to scalar) ----
typedef unsigned long long u64;
__device__ __forceinline__ void fma2(u64& d, u64 a, u64 b) {
    asm("fma.rn.f32x2 %0, %1, %2, %3;" : "=l"(d) : "l"(a), "l"(b), "l"(d));
}
__device__ __forceinline__ void mul2(u64& d, u64 a) {
    asm("mul.rn.f32x2 %0, %1, %2;" : "=l"(d) : "l"(d), "l"(a));
}
__device__ __forceinline__ u64 bcast2(float x) {
    u64 r; asm("mov.b64 %0, {%1, %1};" : "=l"(r) : "f"(x)); return r;
}
__device__ __forceinline__ float2 unpk(u64 v) {
    float2 r; asm("mov.b64 {%0, %1}, %2;" : "=f"(r.x), "=f"(r.y) : "l"(v)); return r;
}

// ---------------- prep kernels ----------------
__global__ __launch_bounds__(256) void repack_kernel(
    const float* __restrict__ wq, const float* __restrict__ wk,
    const float* __restrict__ wv, float* __restrict__ W)
{
    int i = blockIdx.x * 256 + threadIdx.x;
    int m = i >> 10, col = i & 1023;
    int src = (((col >> 6) * MDIM + m) << 6) + (col & 63);
    float* dst = W + (size_t)m * 3072 + col;
    dst[0]    = wq[src];
    dst[1024] = wk[src];
    dst[2048] = wv[src];
}

__global__ __launch_bounds__(256) void repack_qk_kernel(
    const float* __restrict__ wq, const float* __restrict__ wk, float* __restrict__ W)
{
    int i = blockIdx.x * 256 + threadIdx.x;
    int m = i >> 10, col = i & 1023;
    int src = (((col >> 6) * MDIM + m) << 6) + (col & 63);
    W[(size_t)m * 2048 + col]        = wq[src];
    W[(size_t)m * 2048 + 1024 + col] = wk[src];
}

// K slab of QKV -> KT[b*16+h][d][token]  (pure relayout, bit-exact)
__global__ void kt_kernel(const float* __restrict__ src, int stride, float* __restrict__ KT)
{
    __shared__ float tile[32][33];
    int bh = blockIdx.z;
    int b = bh >> 4, h = bh & 15;
    int c0 = blockIdx.x * 32, d0 = blockIdx.y * 32;
    int tx = threadIdx.x, ty = threadIdx.y;
    const float* s = src + (size_t)(b * CDIM) * stride + h * 64;
#pragma unroll
    for (int j = 0; j < 4; j++)
        tile[ty + j * 8][tx] = s[(size_t)(c0 + ty + j * 8) * stride + d0 + tx];
    float* o = KT + (size_t)bh * 64 * CDIM;
    __syncthreads();
#pragma unroll
    for (int j = 0; j < 4; j++)
        o[(size_t)(d0 + ty + j * 8) * CDIM + c0 + tx] = tile[tx][ty + j * 8];
}

__global__ __launch_bounds__(256) void split_kernel(
    const float* __restrict__ in, __nv_bfloat16* __restrict__ hi,
    __nv_bfloat16* __restrict__ lo, int n)
{
    int i = (blockIdx.x * 256 + threadIdx.x) * 4;
    if (i >= n) return;
    float4 v = *(const float4*)(in + i);
    float x[4] = {v.x, v.y, v.z, v.w};
#pragma unroll
    for (int j = 0; j < 4; j++) {
        __nv_bfloat16 h = __float2bfloat16(x[j]);
        hi[i + j] = h;
        lo[i + j] = __float2bfloat16(x[j] - __bfloat162float(h));
    }
}

__global__ void tsplit_kernel(const float* __restrict__ in,
    __nv_bfloat16* __restrict__ hi, __nv_bfloat16* __restrict__ lo, int K, int P)
{
    __shared__ float tile[32][33];
    int p0 = blockIdx.x * 32, k0 = blockIdx.y * 32;
    int tx = threadIdx.x, ty = threadIdx.y;
#pragma unroll
    for (int j = 0; j < 4; j++)
        tile[ty + j * 8][tx] = in[(size_t)(k0 + ty + j * 8) * P + p0 + tx];
    __syncthreads();
#pragma unroll
    for (int j = 0; j < 4; j++) {
        int p = p0 + ty + j * 8, k = k0 + tx;
        float x = tile[tx][ty + j * 8];
        __nv_bfloat16 h = __float2bfloat16(x);
        hi[(size_t)p * K + k] = h;
        lo[(size_t)p * K + k] = __float2bfloat16(x - __bfloat162float(h));
    }
}

__global__ __launch_bounds__(256) void wvsplit_kernel(
    const float* __restrict__ wv, __nv_bfloat16* __restrict__ hi, __nv_bfloat16* __restrict__ lo)
{
    int idx = blockIdx.x * 256 + threadIdx.x;
    int p = idx >> 10, k = idx & 1023;
    float x = wv[(size_t)(((p >> 6) * MDIM + k) << 6) + (p & 63)];
    __nv_bfloat16 h = __float2bfloat16(x);
    hi[idx] = h;
    lo[idx] = __float2bfloat16(x - __bfloat162float(h));
}

// ---------------- 3-pass split-bf16 HMMA GEMM (unchanged) ----------------
#define MMA_STAGE 65536
#define MMA_SMEM  (2*MMA_STAGE + 1024)

__device__ __forceinline__ void stage_load(uint32_t sb,
    const __nv_bfloat16* Ah, const __nv_bfloat16* Al,
    const __nv_bfloat16* Bh, const __nv_bfloat16* Bl,
    int Kdim, int kofs, int rowA, int colB, int t)
{
#pragma unroll
    for (int j = 0; j < 4; j++) {
        int g = j * 256 + t;
        int r = g >> 3, c16 = g & 7;
        uint32_t sw = swz((uint32_t)(r * 128 + c16 * 16));
        size_t ao = (size_t)(rowA + r) * Kdim + kofs + c16 * 8;
        size_t bo = (size_t)(colB + r) * Kdim + kofs + c16 * 8;
        cp16(sb + sw,         Ah + ao);
        cp16(sb + 16384 + sw, Al + ao);
        cp16(sb + 32768 + sw, Bh + bo);
        cp16(sb + 49152 + sw, Bl + bo);
    }
}

__global__ __launch_bounds__(256, 1) void mma_gemm_kernel(
    const __nv_bfloat16* __restrict__ Ah, const __nv_bfloat16* __restrict__ Al,
    const __nv_bfloat16* __restrict__ Bh, const __nv_bfloat16* __restrict__ Bl,
    const float* __restrict__ bias, float* __restrict__ C,
    __nv_bfloat16* __restrict__ outH, __nv_bfloat16* __restrict__ outL,
    int Kdim, int ldc, int relu)
{
    extern __shared__ char dynsm[];
    uint32_t sd = (smem_u32(dynsm) + 1023u) & ~1023u;

    int t = threadIdx.x, wid = t >> 5, lane = t & 31;
    int warp_m = wid & 1, warp_n = wid >> 1;
    int rowA = blockIdx.y * 128, colB = blockIdx.x * 128;

    float acc[4][4][4];
#pragma unroll
    for (int i = 0; i < 4; i++)
#pragma unroll
        for (int j = 0; j < 4; j++)
#pragma unroll
            for (int k = 0; k < 4; k++) acc[i][j][k] = 0.f;

    int rA = lane & 15;
    int cA = (lane >> 4) << 3;
    int rB = (lane & 7) + ((lane >> 4) << 3);
    int cB = lane & 8;

    int nc = Kdim >> 6;
    stage_load(sd, Ah, Al, Bh, Bl, Kdim, 0, rowA, colB, t);
    CP_COMMIT();

    for (int c = 0; c < nc; c++) {
        if (c + 1 < nc) {
            stage_load(sd + ((c + 1) & 1) * MMA_STAGE, Ah, Al, Bh, Bl,
                       Kdim, (c + 1) << 6, rowA, colB, t);
            CP_COMMIT();
            asm volatile("cp.async.wait_group 1;" ::: "memory");
        } else {
            asm volatile("cp.async.wait_group 0;" ::: "memory");
        }
        __syncthreads();
        uint32_t base = sd + (c & 1) * MMA_STAGE;

#pragma unroll
        for (int ks = 0; ks < 4; ks++) {
            int Kc = ks * 16;
            uint32_t aH[4][4], aL[4][4], bH[4][2], bL[4][2];
#pragma unroll
            for (int mt = 0; mt < 4; mt++) {
                uint32_t sw = swz((uint32_t)((warp_m * 64 + mt * 16 + rA) * 128 + (Kc + cA) * 2));
                ldsm4(aH[mt], base + sw);
                ldsm4(aL[mt], base + 16384 + sw);
            }
#pragma unroll
            for (int p = 0; p < 2; p++) {
                uint32_t sw = swz((uint32_t)((warp_n * 32 + p * 16 + rB) * 128 + (Kc + cB) * 2));
                uint32_t q[4];
                ldsm4(q, base + 32768 + sw);
                bH[2*p][0] = q[0]; bH[2*p][1] = q[1]; bH[2*p+1][0] = q[2]; bH[2*p+1][1] = q[3];
                ldsm4(q, base + 49152 + sw);
                bL[2*p][0] = q[0]; bL[2*p][1] = q[1]; bL[2*p+1][0] = q[2]; bL[2*p+1][1] = q[3];
            }
#pragma unroll
            for (int mt = 0; mt < 4; mt++)
#pragma unroll
                for (int nt = 0; nt < 4; nt++) {
                    mma16816(acc[mt][nt], aH[mt], bH[nt]);
                    mma16816(acc[mt][nt], aH[mt], bL[nt]);
                    mma16816(acc[mt][nt], aL[mt], bH[nt]);
                }
        }
        __syncthreads();
    }

    int r0 = rowA + warp_m * 64 + (lane >> 2);
    int c0 = colB + warp_n * 32 + (lane & 3) * 2;
#pragma unroll
    for (int mt = 0; mt < 4; mt++) {
#pragma unroll
        for (int nt = 0; nt < 4; nt++) {
            int col = c0 + nt * 8;
            float bb0 = 0.f, bb1 = 0.f;
            if (bias) { bb0 = bias[col]; bb1 = bias[col + 1]; }
            float v0 = acc[mt][nt][0] + bb0;
            float v1 = acc[mt][nt][1] + bb1;
            float v2 = acc[mt][nt][2] + bb0;
            float v3 = acc[mt][nt][3] + bb1;
            if (relu) {
                v0 = fmaxf(v0, 0.f); v1 = fmaxf(v1, 0.f);
                v2 = fmaxf(v2, 0.f); v3 = fmaxf(v3, 0.f);
            }
            size_t ra = (size_t)(r0 + mt * 16) * ldc + col;
            size_t rb = ra + 8 * (size_t)ldc;
            if (outH) {
                __nv_bfloat162 h, l;
                h.x = __float2bfloat16(v0); h.y = __float2bfloat16(v1);
                l.x = __float2bfloat16(v0 - __bfloat162float(h.x));
                l.y = __float2bfloat16(v1 - __bfloat162float(h.y));
                *(__nv_bfloat162*)&outH[ra] = h;
                *(__nv_bfloat162*)&outL[ra] = l;
                h.x = __float2bfloat16(v2); h.y = __float2bfloat16(v3);
                l.x = __float2bfloat16(v2 - __bfloat162float(h.x));
                l.y = __float2bfloat16(v3 - __bfloat162float(h.y));
                *(__nv_bfloat162*)&outH[rb] = h;
                *(__nv_bfloat162*)&outL[rb] = l;
            } else {
                *(float2*)&C[ra] = make_float2(v0, v1);
                *(float2*)&C[rb] = make_float2(v2, v3);
            }
        }
    }
}

// ---------------- fp32 SGEMM, packed-f32x2 inner loop (bit-identical per element) ----------------
__global__ __launch_bounds__(256) void sgemm_kernel(
    const float* __restrict__ A, const float* __restrict__ B,
    float* __restrict__ C, int Kdim, int lda, int ldb, int ldc)
{
    __shared__ float sA[16][128];
    __shared__ float sB[16][128];

    int t = threadIdx.x;
    int tx = t & 15, ty = t >> 4;
    int rowBase = blockIdx.y * 128, colBase = blockIdx.x * 128;

    u64 acc2[8][4];
#pragma unroll
    for (int i = 0; i < 8; i++)
#pragma unroll
        for (int j = 0; j < 4; j++) acc2[i][j] = 0ull;

    int arow = t >> 1, acol = (t & 1) * 4;
    int brow = t >> 5, bcol = (t & 31) * 4;
    const float* Aptr = A + (size_t)(rowBase + arow) * lda + acol;
    const float* Bptr = B + (size_t)brow * ldb + colBase + bcol;

    for (int kt = 0; kt < Kdim; kt += 16) {
        float4 a0 = *(const float4*)(Aptr);
        float4 a1 = *(const float4*)(Aptr + 8);
        float4 b0 = *(const float4*)(Bptr);
        float4 b1 = *(const float4*)(Bptr + 8 * (size_t)ldb);
        sA[acol+0][arow]=a0.x; sA[acol+1][arow]=a0.y; sA[acol+2][arow]=a0.z; sA[acol+3][arow]=a0.w;
        sA[acol+8][arow]=a1.x; sA[acol+9][arow]=a1.y; sA[acol+10][arow]=a1.z; sA[acol+11][arow]=a1.w;
        *(float4*)&sB[brow][bcol] = b0;
        *(float4*)&sB[brow+8][bcol] = b1;
        __syncthreads();
#pragma unroll
        for (int k = 0; k < 16; k++) {
            float4 x0 = *(const float4*)&sA[k][ty*4];
            float4 x1 = *(const float4*)&sA[k][64+ty*4];
            ulonglong2 yb0 = *(const ulonglong2*)&sB[k][tx*4];
            ulonglong2 yb1 = *(const ulonglong2*)&sB[k][64+tx*4];
            float av[8] = {x0.x,x0.y,x0.z,x0.w,x1.x,x1.y,x1.z,x1.w};
#pragma unroll
            for (int i = 0; i < 8; i++) {
                u64 ai = bcast2(av[i]);
                fma2(acc2[i][0], ai, yb0.x);
                fma2(acc2[i][1], ai, yb0.y);
                fma2(acc2[i][2], ai, yb1.x);
                fma2(acc2[i][3], ai, yb1.y);
            }
        }
        __syncthreads();
        Aptr += 16;
        Bptr += 16 * (size_t)ldb;
    }
    int c0 = colBase + tx * 4, c1 = colBase + 64 + tx * 4;
#pragma unroll
    for (int i = 0; i < 8; i++) {
        int r = rowBase + ((i < 4) ? (ty*4+i) : (64+ty*4+i-4));
        float2 p0 = unpk(acc2[i][0]), p1 = unpk(acc2[i][1]);
        float2 p2 = unpk(acc2[i][2]), p3 = unpk(acc2[i][3]);
        *(float4*)&C[(size_t)r*ldc + c0] = make_float4(p0.x, p0.y, p1.x, p1.y);
        *(float4*)&C[(size_t)r*ldc + c1] = make_float4(p2.x, p2.y, p3.x, p3.y);
    }
}

// ---------------- attention v5: optional pre-split bf16 output epilogue ----------------
#define QP 68
#define SQT_OFF   0
#define SKT_OFF   4352
#define SP_OFF    13056
#define SV_OFF    17408
#define ATT_SMEM_BYTES ((SV_OFF + 2*4096) * 4)

__global__ __launch_bounds__(256, 2) void attn_kernel(
    const float* __restrict__ Qb, int qs,
    const float* __restrict__ KTb,
    const float* __restrict__ Vb, int vs,
    float* __restrict__ AO,
    __nv_bfloat16* __restrict__ soH, __nv_bfloat16* __restrict__ soL,
    int masked)
{
    extern __shared__ float sm[];
    float* sQT = sm + SQT_OFF;
    float* sP  = sm + SP_OFF;
    uint32_t sbase = smem_u32(sm);
    uint32_t kt_b = sbase + SKT_OFF * 4;
    uint32_t v_b0 = sbase + SV_OFF * 4;

    int t = threadIdx.x;
    int tx = t & 15, ty = t >> 4;
    int tx4 = tx * 4, ty4 = ty * 4;
    int q0 = blockIdx.x * 64;
    int b = blockIdx.y >> 4, h = blockIdx.y & 15;

    const float* qbase  = Qb + (size_t)b * CDIM * qs + h * 64;
    const float* ktbase = KTb + (size_t)blockIdx.y * 64 * CDIM;
    const float* vbase  = Vb + (size_t)b * CDIM * vs + h * 64;

#pragma unroll
    for (int it = 0; it < 4; it++) {
        int idx = it * 256 + t;
        int r = idx >> 4, ch = idx & 15;
        uint32_t kdst = kt_b + (uint32_t)(r * QP * 4 + ((ch ^ ((r >> 2) & 7)) * 16));
        cp16(kdst, ktbase + (size_t)r * CDIM + ch * 4);
        cp16(v_b0 + r * 256 + ch * 16, vbase + (size_t)r * vs + ch * 4);
    }
    CP_COMMIT();

#pragma unroll
    for (int it = 0; it < 4; it++) {
        int idx = it * 256 + t;
        int qi = idx >> 4, dg = idx & 15;
        float4 v = *(const float4*)&qbase[(size_t)(q0 + qi) * qs + dg * 4];
        sQT[(dg * 4 + 0) * QP + qi] = v.x;
        sQT[(dg * 4 + 1) * QP + qi] = v.y;
        sQT[(dg * 4 + 2) * QP + qi] = v.z;
        sQT[(dg * 4 + 3) * QP + qi] = v.w;
    }

    float m_run[4], l_run[4];
    u64 o2[4][2];
#pragma unroll
    for (int i = 0; i < 4; i++) {
        m_run[i] = -INFINITY; l_run[i] = 0.f;
        o2[i][0] = 0ull; o2[i][1] = 0ull;
    }

    for (int kt = 0; kt < 32; kt++) {
        int cur = kt & 1;
        int k0 = kt * 64;
        asm volatile("cp.async.wait_group 0;" ::: "memory");
        __syncthreads();

        if (kt + 1 < 32) {
            int k0n = k0 + 64;
            uint32_t kdstb = kt_b + (cur ^ 1) * 4352 * 4;
            uint32_t vdst  = v_b0 + (cur ^ 1) * 16384;
#pragma unroll
            for (int it = 0; it < 4; it++) {
                int idx = it * 256 + t;
                int r = idx >> 4, ch = idx & 15;
                uint32_t kdst = kdstb + (uint32_t)(r * QP * 4 + ((ch ^ ((r >> 2) & 7)) * 16));
                cp16(kdst, ktbase + (size_t)r * CDIM + k0n + ch * 4);
                cp16(vdst + r * 256 + ch * 16, vbase + (size_t)(k0n + r) * vs + ch * 4);
            }
            CP_COMMIT();
        }

        const float* sKT = sm + SKT_OFF + cur * 4352;

        u64 s2[4][2];
#pragma unroll
        for (int i = 0; i < 4; i++) { s2[i][0] = 0ull; s2[i][1] = 0ull; }

#pragma unroll 4
        for (int dg = 0; dg < 16; dg++) {
            int colx = tx4 ^ ((dg & 7) << 2);
#pragma unroll
            for (int e = 0; e < 4; e++) {
                int d = dg * 4 + e;
                float4 a = *(const float4*)&sQT[d * QP + ty4];
                ulonglong2 kp = *(const ulonglong2*)&sKT[d * QP + colx];
                u64 b0 = bcast2(a.x), b1 = bcast2(a.y);
                u64 b2 = bcast2(a.z), b3 = bcast2(a.w);
                fma2(s2[0][0], b0, kp.x); fma2(s2[0][1], b0, kp.y);
                fma2(s2[1][0], b1, kp.x); fma2(s2[1][1], b1, kp.y);
                fma2(s2[2][0], b2, kp.x); fma2(s2[2][1], b2, kp.y);
                fma2(s2[3][0], b3, kp.x); fma2(s2[3][1], b3, kp.y);
            }
        }

#pragma unroll
        for (int i = 0; i < 4; i++) {
            float2 u0 = unpk(s2[i][0]), u1 = unpk(s2[i][1]);
            float s0 = u0.x, s1 = u0.y, sv2 = u1.x, s3 = u1.y;
            int qg = q0 + ty4 + i;
            if (masked) {
                if ((k0 + tx4 + 0) <= qg) s0 -= 100.f;
                if ((k0 + tx4 + 1) <= qg) s1 -= 100.f;
                if ((k0 + tx4 + 2) <= qg) sv2 -= 100.f;
                if ((k0 + tx4 + 3) <= qg) s3 -= 100.f;
            }
            s0 *= 0.125f; s1 *= 0.125f; sv2 *= 0.125f; s3 *= 0.125f;
            float mx = fmaxf(fmaxf(s0, s1), fmaxf(sv2, s3));
#pragma unroll
            for (int off = 8; off >= 1; off >>= 1)
                mx = fmaxf(mx, __shfl_xor_sync(0xffffffffu, mx, off, 16));
            float mnew = fmaxf(m_run[i], mx);
            float p0 = expf(s0 - mnew);
            float p1 = expf(s1 - mnew);
            float p2 = expf(sv2 - mnew);
            float p3 = expf(s3 - mnew);
            float rs = p0 + p1 + p2 + p3;
#pragma unroll
            for (int off = 8; off >= 1; off >>= 1)
                rs += __shfl_xor_sync(0xffffffffu, rs, off, 16);
            float corr = expf(m_run[i] - mnew);
            l_run[i] = l_run[i] * corr + rs;
            m_run[i] = mnew;
            u64 c2 = bcast2(corr);
            mul2(o2[i][0], c2);
            mul2(o2[i][1], c2);
            *(float4*)&sP[(ty4 + i) * QP + tx4] = make_float4(p0, p1, p2, p3);
        }
        __syncthreads();

        const float* sVc = sm + SV_OFF + cur * 4096;
#pragma unroll 4
        for (int kj0 = 0; kj0 < 64; kj0 += 4) {
            float4 pa0 = *(const float4*)&sP[(ty4 + 0) * QP + kj0];
            float4 pa1 = *(const float4*)&sP[(ty4 + 1) * QP + kj0];
            float4 pa2 = *(const float4*)&sP[(ty4 + 2) * QP + kj0];
            float4 pa3 = *(const float4*)&sP[(ty4 + 3) * QP + kj0];
#pragma unroll
            for (int e = 0; e < 4; e++) {
                ulonglong2 vp = *(const ulonglong2*)&sVc[(kj0 + e) * 64 + tx4];
                u64 b0 = bcast2(((const float*)&pa0)[e]);
                u64 b1 = bcast2(((const float*)&pa1)[e]);
                u64 b2 = bcast2(((const float*)&pa2)[e]);
                u64 b3 = bcast2(((const float*)&pa3)[e]);
                fma2(o2[0][0], b0, vp.x); fma2(o2[0][1], b0, vp.y);
                fma2(o2[1][0], b1, vp.x); fma2(o2[1][1], b1, vp.y);
                fma2(o2[2][0], b2, vp.x); fma2(o2[2][1], b2, vp.y);
                fma2(o2[3][0], b3, vp.x); fma2(o2[3][1], b3, vp.y);
            }
        }
    }

#pragma unroll
    for (int i = 0; i < 4; i++) {
        float inv = 1.f / l_run[i];
        float2 w0 = unpk(o2[i][0]), w1 = unpk(o2[i][1]);
        float v0 = w0.x * inv, v1 = w0.y * inv, v2 = w1.x * inv, v3 = w1.y * inv;
        size_t row = (size_t)(b * CDIM + q0 + ty4 + i) * MDIM + h * 64 + tx4;
        if (soH) {
            __nv_bfloat162 hh, ll;
            hh.x = __float2bfloat16(v0); hh.y = __float2bfloat16(v1);
            ll.x = __float2bfloat16(v0 - __bfloat162float(hh.x));
            ll.y = __float2bfloat16(v1 - __bfloat162float(hh.y));
            *(__nv_bfloat162*)&soH[row] = hh;
            *(__nv_bfloat162*)&soL[row] = ll;
            hh.x = __float2bfloat16(v2); hh.y = __float2bfloat16(v3);
            ll.x = __float2bfloat16(v2 - __bfloat162float(hh.x));
            ll.y = __float2bfloat16(v3 - __bfloat162float(hh.y));
            *(__nv_bfloat162*)&soH[row + 2] = hh;
            *(__nv_bfloat162*)&soL[row + 2] = ll;
        } else {
            AO[row + 0] = v0;
            AO[row + 1] = v1;
            AO[row + 2] = v2;
            AO[row + 3] = v3;
        }
    }
}

// ---------------- residual add + LayerNorm (optional fused split output) ----------------
__global__ __launch_bounds__(256) void addln_kernel(
    const float* __restrict__ X, const float* __restrict__ Y,
    const float* __restrict__ g, const float* __restrict__ bta,
    float* __restrict__ out,
    __nv_bfloat16* __restrict__ soH, __nv_bfloat16* __restrict__ soL)
{
    __shared__ float red[8];
    int row = blockIdx.x;
    int t = threadIdx.x;
    int lane = t & 31, wid = t >> 5;
    const float* xr = X + (size_t)row * MDIM;
    const float* yr = Y + (size_t)row * MDIM;

    float v[4];
#pragma unroll
    for (int i = 0; i < 4; i++) v[i] = xr[t + 256 * i] + yr[t + 256 * i];

    float s = v[0] + v[1] + v[2] + v[3];
#pragma unroll
    for (int off = 16; off >= 1; off >>= 1) s += __shfl_xor_sync(0xffffffffu, s, off);
    if (lane == 0) red[wid] = s;
    __syncthreads();
    float tot = 0.f;
#pragma unroll
    for (int i = 0; i < 8; i++) tot += red[i];
    float mu = tot * (1.f / 1024.f);
    __syncthreads();

    float q = 0.f;
#pragma unroll
    for (int i = 0; i < 4; i++) { float d = v[i] - mu; q += d * d; }
#pragma unroll
    for (int off = 16; off >= 1; off >>= 1) q += __shfl_xor_sync(0xffffffffu, q, off);
    if (lane == 0) red[wid] = q;
    __syncthreads();
    float qtot = 0.f;
#pragma unroll
    for (int i = 0; i < 8; i++) qtot += red[i];
    float inv = rsqrtf(qtot * (1.f / 1024.f) + LN_EPS);

#pragma unroll
    for (int i = 0; i < 4; i++) {
        int c = t + 256 * i;
        float o = (v[i] - mu) * inv * g[c] + bta[c];
        out[(size_t)row * MDIM + c] = o;
        if (soH) {
            __nv_bfloat16 h = __float2bfloat16(o);
            soH[(size_t)row * MDIM + c] = h;
            soL[(size_t)row * MDIM + c] = __float2bfloat16(o - __bfloat162float(h));
        }
    }
}

// ---------------- launcher: two-stream graph with fork/join ----------------
extern "C" void kernel_launch(void* const* d_in, const int* in_sizes, int n_in,
                              void* d_out, int out_size)
{
    const float* enc = (const float*)d_in[0];
    const float* x   = (const float*)d_in[1];
    const float* wq1 = (const float*)d_in[2];
    const float* wk1 = (const float*)d_in[3];
    const float* wv1 = (const float*)d_in[4];
    const float* wo1 = (const float*)d_in[5];
    const float* g1  = (const float*)d_in[6];
    const float* b1  = (const float*)d_in[7];
    const float* wq2 = (const float*)d_in[8];
    const float* wk2 = (const float*)d_in[9];
    const float* wv2 = (const float*)d_in[10];
    const float* wo2 = (const float*)d_in[11];
    const float* g2  = (const float*)d_in[12];
    const float* b2  = (const float*)d_in[13];
    const float* fw1 = (const float*)d_in[14];
    const float* fb1 = (const float*)d_in[15];
    const float* fw2 = (const float*)d_in[16];
    const float* fb2 = (const float*)d_in[17];
    const float* g3  = (const float*)d_in[18];
    const float* b3  = (const float*)d_in[19];
    float* out = (float*)d_out;

    float *W1, *W2, *QKV, *KT, *V, *AO, *T, *N1, *N2;
    __nv_bfloat16 *Ah, *Al, *Wvh, *Wvl, *Wo2h, *Wo2l, *F1h, *F1l, *F2h, *F2l, *Ch, *Cl;
    cudaGetSymbolAddress((void**)&W1, g_W1);
    cudaGetSymbolAddress((void**)&W2, g_W2);
    cudaGetSymbolAddress((void**)&QKV, g_QKV);
    cudaGetSymbolAddress((void**)&KT, g_KT);
    cudaGetSymbolAddress((void**)&V,  g_V);
    cudaGetSymbolAddress((void**)&AO, g_AO);
    cudaGetSymbolAddress((void**)&T,  g_T);
    cudaGetSymbolAddress((void**)&N1, g_N1);
    cudaGetSymbolAddress((void**)&N2, g_N2);
    cudaGetSymbolAddress((void**)&Ah, g_Ah);
    cudaGetSymbolAddress((void**)&Al, g_Al);
    cudaGetSymbolAddress((void**)&Wvh, g_Wvh);
    cudaGetSymbolAddress((void**)&Wvl, g_Wvl);
    cudaGetSymbolAddress((void**)&Wo2h, g_Wo2h);
    cudaGetSymbolAddress((void**)&Wo2l, g_Wo2l);
    cudaGetSymbolAddress((void**)&F1h, g_F1h);
    cudaGetSymbolAddress((void**)&F1l, g_F1l);
    cudaGetSymbolAddress((void**)&F2h, g_F2h);
    cudaGetSymbolAddress((void**)&F2l, g_F2l);
    cudaGetSymbolAddress((void**)&Ch, g_Ch);
    cudaGetSymbolAddress((void**)&Cl, g_Cl);

    cudaFuncSetAttribute(attn_kernel, cudaFuncAttributeMaxDynamicSharedMemorySize, ATT_SMEM_BYTES);
    cudaFuncSetAttribute(mma_gemm_kernel, cudaFuncAttributeMaxDynamicSharedMemorySize, MMA_SMEM);

    // one-time infra (created on the first, non-captured call; reused thereafter)
    static cudaStream_t s2 = nullptr;
    static cudaEvent_t ev0 = nullptr, evW = nullptr, ev1 = nullptr;
    if (s2 == nullptr) {
        cudaStreamCreateWithFlags(&s2, cudaStreamNonBlocking);
        cudaEventCreateWithFlags(&ev0, cudaEventDisableTiming);
        cudaEventCreateWithFlags(&evW, cudaEventDisableTiming);
        cudaEventCreateWithFlags(&ev1, cudaEventDisableTiming);
    }

    dim3 tsb(32, 8);
    dim3 ktg(64, 2, 32);
    const int NM = NTOK * MDIM;

    // ---- fork side stream: weight preps + V2 GEMM (independent of self-attn) ----
    cudaEventRecord(ev0, 0);
    cudaStreamWaitEvent(s2, ev0, 0);
    repack_qk_kernel<<<4096, 256, 0, s2>>>(wq2, wk2, W2);
    cudaEventRecord(evW, s2);
    wvsplit_kernel<<<4096, 256, 0, s2>>>(wv2, Wvh, Wvl);
    split_kernel<<<4096, 256, 0, s2>>>(enc, Ah, Al, NM);
    mma_gemm_kernel<<<dim3(8, 32), 256, MMA_SMEM, s2>>>(
        Ah, Al, Wvh, Wvl, nullptr, V, nullptr, nullptr, 1024, 1024, 0);
    tsplit_kernel<<<dim3(32, 32), tsb, 0, s2>>>(wo2, Wo2h, Wo2l, 1024, 1024);
    tsplit_kernel<<<dim3(128, 32), tsb, 0, s2>>>(fw1, F1h, F1l, 1024, 4096);
    tsplit_kernel<<<dim3(32, 128), tsb, 0, s2>>>(fw2, F2h, F2l, 4096, 1024);
    cudaEventRecord(ev1, s2);

    // ---- main stream: masked self attention (all fp32 — logit-critical) ----
    repack_kernel<<<4096, 256>>>(wq1, wk1, wv1, W1);
    sgemm_kernel<<<dim3(24, 32), 256>>>(x, W1, QKV, 1024, 1024, 3072, 3072);
    kt_kernel<<<ktg, tsb>>>(QKV + 1024, 3072, KT);
    attn_kernel<<<dim3(32, 32), 256, ATT_SMEM_BYTES>>>(
        QKV, 3072, KT, QKV + 2048, 3072, AO, nullptr, nullptr, 1);
    sgemm_kernel<<<dim3(8, 32), 256>>>(AO, wo1, T, 1024, 1024, 1024, 1024);
    addln_kernel<<<4096, 256>>>(x, T, g1, b1, N1, nullptr, nullptr);

    // ---- cross attention: Q/K fp32, V2 (from s2), wo2 on tensor ----
    cudaStreamWaitEvent(0, evW, 0);
    sgemm_kernel<<<dim3(8, 32), 256>>>(N1, W2, QKV, 1024, 1024, 2048, 2048);
    sgemm_kernel<<<dim3(8, 32), 256>>>(enc, W2 + 1024, QKV + 1024, 1024, 1024, 2048, 2048);
    kt_kernel<<<ktg, tsb>>>(QKV + 1024, 2048, KT);
    cudaStreamWaitEvent(0, ev1, 0);      // join: V ready, all weight splits ready
    attn_kernel<<<dim3(32, 32), 256, ATT_SMEM_BYTES>>>(
        QKV, 2048, KT, V, 1024, nullptr, Ah, Al, 0);   // writes pre-split output
    mma_gemm_kernel<<<dim3(8, 32), 256, MMA_SMEM>>>(
        Ah, Al, Wo2h, Wo2l, nullptr, T, nullptr, nullptr, 1024, 1024, 0);
    addln_kernel<<<4096, 256>>>(N1, T, g2, b2, N2, Ah, Al);   // fused split for FFN1

    // ---- FFN (tensor) ----
    mma_gemm_kernel<<<dim3(32, 32), 256, MMA_SMEM>>>(
        Ah, Al, F1h, F1l, fb1, nullptr, Ch, Cl, 1024, 4096, 1);
    mma_gemm_kernel<<<dim3(8, 32), 256, MMA_SMEM>>>(
        Ch, Cl, F2h, F2l, fb2, T, nullptr, nullptr, 4096, 1024, 0);
    addln_kernel<<<4096, 256>>>(N2, T, g3, b3, out, nullptr, nullptr);
}